// round 12
// baseline (speedup 1.0000x reference)
#include <cuda_runtime.h>
#include <cuda_bf16.h>
#include <math.h>

#define N_NODES 50000
#define E_EDGES 800000
#define ET (E_EDGES + N_NODES)   /* 850000 edges incl. self loops */
#define HID 128
#define HEADS 8
#define C1 16
#define OUT_DIM 64
#define NEG_SLOPE 0.2f
#define NB_SCAN ((N_NODES + 1023) / 1024)   /* 49 scan tiles */

// ---------------- scratch (device globals; no allocation) ----------------
__device__ __align__(16) float g_h1[N_NODES * HID];    // layer1 projection (fp32, for scores)
__device__ __align__(16) __nv_bfloat16 g_h1b[N_NODES * HID];   // bf16 copy (gather payload)
__device__ __align__(16) float g_out1[N_NODES * HID];  // layer1 output (post-ELU)
__device__ __align__(16) float g_h2[N_NODES * OUT_DIM];
__device__ __align__(16) __nv_bfloat16 g_h2b[N_NODES * OUT_DIM];
__device__ float g_as1[N_NODES * HEADS];
__device__ float g_ad1[N_NODES * HEADS];
__device__ float g_as2[N_NODES];
__device__ float g_ad2[N_NODES];
__device__ int   g_src[ET];
__device__ int   g_dst[ET];
__device__ int   g_es[ET];          // src ids sorted by dst (CSR values)
__device__ int   g_cnt[N_NODES];
__device__ int   g_off[N_NODES + 1];
__device__ int   g_cur[N_NODES];
__device__ int   g_bsum[NB_SCAN];
__device__ int   g_boff[NB_SCAN];
__device__ int   g_is64;

// ---------------- side stream for CSR-build / GEMM overlap ----------------
namespace {
struct AuxStreams {
    cudaStream_t s2 = 0;
    cudaEvent_t  fork = 0, join = 0;
    bool ok = false;
    AuxStreams() {
        if (cudaStreamCreateWithFlags(&s2, cudaStreamNonBlocking) == cudaSuccess &&
            cudaEventCreateWithFlags(&fork, cudaEventDisableTiming) == cudaSuccess &&
            cudaEventCreateWithFlags(&join, cudaEventDisableTiming) == cudaSuccess) {
            ok = true;
        } else {
            s2 = 0;
            ok = false;
        }
    }
};
AuxStreams g_aux;
}

// ---------------- tf32 helpers ----------------
__device__ __forceinline__ float f2tf32f(float f) {
    unsigned r;
    asm("cvt.rna.tf32.f32 %0, %1;" : "=r"(r) : "f"(f));
    return __uint_as_float(r);
}
__device__ __forceinline__ void mma_tf32(float* d, unsigned a0, unsigned a1,
                                         unsigned a2, unsigned a3,
                                         unsigned b0, unsigned b1) {
    asm volatile(
        "mma.sync.aligned.m16n8k8.row.col.f32.tf32.tf32.f32 "
        "{%0,%1,%2,%3}, {%4,%5,%6,%7}, {%8,%9}, {%0,%1,%2,%3};"
        : "+f"(d[0]), "+f"(d[1]), "+f"(d[2]), "+f"(d[3])
        : "r"(a0), "r"(a1), "r"(a2), "r"(a3), "r"(b0), "r"(b1));
}

// ---------------- edge dtype detection ----------------
__global__ void detect_kernel(const unsigned long long* __restrict__ e64) {
    __shared__ int bad;
    if (threadIdx.x == 0) bad = 0;
    __syncthreads();
    unsigned long long v = e64[threadIdx.x];  // blockDim.x = 1024
    if (v >= (unsigned long long)N_NODES) atomicOr(&bad, 1);
    __syncthreads();
    if (threadIdx.x == 0) g_is64 = bad ? 0 : 1;
}

__global__ void zerocnt_kernel() {
    int i = blockIdx.x * blockDim.x + threadIdx.x;
    if (i < N_NODES) g_cnt[i] = 0;
}

__global__ void convert_hist_kernel(const void* __restrict__ ei) {
    int t = blockIdx.x * blockDim.x + threadIdx.x;
    if (t >= ET) return;
    int s, d;
    if (t >= E_EDGES) {
        s = d = t - E_EDGES;
    } else if (g_is64) {
        const long long* p = (const long long*)ei;
        s = (int)p[t];
        d = (int)p[E_EDGES + t];
    } else {
        const int* p = (const int*)ei;
        s = p[t];
        d = p[E_EDGES + t];
    }
    g_src[t] = s;
    g_dst[t] = d;
    atomicAdd(&g_cnt[d], 1);
}

// ---------------- chip-wide 3-phase exclusive scan of g_cnt ----------------
__global__ void scan_local_kernel() {
    __shared__ int sh[1024];
    int t = threadIdx.x;
    int i = blockIdx.x * 1024 + t;
    int v = (i < N_NODES) ? g_cnt[i] : 0;
    sh[t] = v;
    __syncthreads();
    for (int o = 1; o < 1024; o <<= 1) {
        int cur = sh[t];
        int idx = (t >= o) ? (t - o) : 0;   // always valid (no speculative OOB LDS)
        int u = sh[idx];
        u = (t >= o) ? u : 0;
        __syncthreads();
        sh[t] = cur + u;
        __syncthreads();
    }
    if (i < N_NODES) g_off[i] = sh[t] - v;  // exclusive within tile
    if (t == 1023) g_bsum[blockIdx.x] = sh[1023];
}

__global__ void scan_bsum_kernel() {
    __shared__ int sh[64];
    int t = threadIdx.x;   // blockDim.x = 64 >= NB_SCAN
    int v = (t < NB_SCAN) ? g_bsum[t] : 0;
    sh[t] = v;
    __syncthreads();
    for (int o = 1; o < 64; o <<= 1) {
        int cur = sh[t];
        int idx = (t >= o) ? (t - o) : 0;
        int u = sh[idx];
        u = (t >= o) ? u : 0;
        __syncthreads();
        sh[t] = cur + u;
        __syncthreads();
    }
    if (t < NB_SCAN) g_boff[t] = sh[t] - v;  // exclusive
}

__global__ void addoff_kernel() {
    int i = blockIdx.x * blockDim.x + threadIdx.x;
    if (i < N_NODES) {
        int o = g_off[i] + g_boff[i >> 10];
        g_off[i] = o;
        g_cur[i] = o;
    }
    if (i == 0) g_off[N_NODES] = ET;
}

__global__ void scatter_kernel() {
    int t = blockIdx.x * blockDim.x + threadIdx.x;
    if (t >= ET) return;
    int d = g_dst[t];
    int pos = atomicAdd(&g_cur[d], 1);
    g_es[pos] = g_src[t];
}

// ---------------- tf32 tensor-core GEMM, layer 1 (128x128 tile) ------------
__global__ void __launch_bounds__(256) gemm1_kernel(const float* __restrict__ X,
                                                    const float* __restrict__ W) {
    __shared__ float Xs[128][36];   // pad 36: A-frag bank = (4g+tg), conflict-free
    __shared__ float Ws[32][136];   // pad 136: B-frag bank = (8tg+g), conflict-free
    const int tid = threadIdx.x;
    const int warp = tid >> 5, lane = tid & 31;
    const int g = lane >> 2, tg = lane & 3;
    const int base = blockIdx.x * 128;
    const int row0 = warp * 16;

    float d[16][4];
#pragma unroll
    for (int nt = 0; nt < 16; nt++)
#pragma unroll
        for (int j = 0; j < 4; j++) d[nt][j] = 0.0f;

    const int lr = tid >> 1, lh = tid & 1;   // X loader
    const int kw = tid >> 3, seg = tid & 7;  // W loader

    for (int k0 = 0; k0 < 128; k0 += 32) {
        {
            int node = base + lr; if (node >= N_NODES) node = N_NODES - 1;
            const float4* xr = (const float4*)(X + (size_t)node * 128 + k0 + lh * 16);
#pragma unroll
            for (int c = 0; c < 4; c++) {
                float4 v = xr[c];
                int kk = lh * 16 + c * 4;
                Xs[lr][kk + 0] = f2tf32f(v.x); Xs[lr][kk + 1] = f2tf32f(v.y);
                Xs[lr][kk + 2] = f2tf32f(v.z); Xs[lr][kk + 3] = f2tf32f(v.w);
            }
        }
        {
            const float4* wr = (const float4*)(W + (size_t)(k0 + kw) * 128 + seg * 16);
#pragma unroll
            for (int c = 0; c < 4; c++) {
                float4 v = wr[c];
                int cc = seg * 16 + c * 4;
                Ws[kw][cc + 0] = f2tf32f(v.x); Ws[kw][cc + 1] = f2tf32f(v.y);
                Ws[kw][cc + 2] = f2tf32f(v.z); Ws[kw][cc + 3] = f2tf32f(v.w);
            }
        }
        __syncthreads();
#pragma unroll
        for (int ks = 0; ks < 4; ks++) {
            int kk = ks * 8;
            unsigned a0 = __float_as_uint(Xs[row0 + g][kk + tg]);
            unsigned a1 = __float_as_uint(Xs[row0 + g + 8][kk + tg]);
            unsigned a2 = __float_as_uint(Xs[row0 + g][kk + tg + 4]);
            unsigned a3 = __float_as_uint(Xs[row0 + g + 8][kk + tg + 4]);
#pragma unroll
            for (int nt = 0; nt < 16; nt++) {
                unsigned b0 = __float_as_uint(Ws[kk + tg][nt * 8 + g]);
                unsigned b1 = __float_as_uint(Ws[kk + tg + 4][nt * 8 + g]);
                mma_tf32(d[nt], a0, a1, a2, a3, b0, b1);
            }
        }
        __syncthreads();
    }
#pragma unroll
    for (int nt = 0; nt < 16; nt++) {
        int c = nt * 8 + 2 * tg;
        int n1 = base + row0 + g;
        int n2 = n1 + 8;
        if (n1 < N_NODES) {
            *(float2*)&g_h1[(size_t)n1 * 128 + c] = make_float2(d[nt][0], d[nt][1]);
            __nv_bfloat162 p = __floats2bfloat162_rn(d[nt][0], d[nt][1]);
            *(unsigned*)&g_h1b[(size_t)n1 * 128 + c] = *(unsigned*)&p;
        }
        if (n2 < N_NODES) {
            *(float2*)&g_h1[(size_t)n2 * 128 + c] = make_float2(d[nt][2], d[nt][3]);
            __nv_bfloat162 p = __floats2bfloat162_rn(d[nt][2], d[nt][3]);
            *(unsigned*)&g_h1b[(size_t)n2 * 128 + c] = *(unsigned*)&p;
        }
    }
}

// ---------------- tf32 tensor-core GEMM, layer 2 (128x64 tile) -------------
__global__ void __launch_bounds__(256) gemm2_kernel(const float* __restrict__ W) {
    __shared__ float Xs[128][36];
    __shared__ float Ws[32][72];    // pad 72: B-frag bank = (8tg+g), conflict-free
    const int tid = threadIdx.x;
    const int warp = tid >> 5, lane = tid & 31;
    const int g = lane >> 2, tg = lane & 3;
    const int base = blockIdx.x * 128;
    const int row0 = warp * 16;

    float d[8][4];
#pragma unroll
    for (int nt = 0; nt < 8; nt++)
#pragma unroll
        for (int j = 0; j < 4; j++) d[nt][j] = 0.0f;

    const int lr = tid >> 1, lh = tid & 1;   // X loader
    const int kw = tid >> 3, seg = tid & 7;  // W loader

    for (int k0 = 0; k0 < 128; k0 += 32) {
        {
            int node = base + lr; if (node >= N_NODES) node = N_NODES - 1;
            const float4* xr = (const float4*)(g_out1 + (size_t)node * 128 + k0 + lh * 16);
#pragma unroll
            for (int c = 0; c < 4; c++) {
                float4 v = xr[c];
                int kk = lh * 16 + c * 4;
                Xs[lr][kk + 0] = f2tf32f(v.x); Xs[lr][kk + 1] = f2tf32f(v.y);
                Xs[lr][kk + 2] = f2tf32f(v.z); Xs[lr][kk + 3] = f2tf32f(v.w);
            }
        }
        {
            const float4* wr = (const float4*)(W + (size_t)(k0 + kw) * 64 + seg * 8);
#pragma unroll
            for (int c = 0; c < 2; c++) {
                float4 v = wr[c];
                int cc = seg * 8 + c * 4;
                Ws[kw][cc + 0] = f2tf32f(v.x); Ws[kw][cc + 1] = f2tf32f(v.y);
                Ws[kw][cc + 2] = f2tf32f(v.z); Ws[kw][cc + 3] = f2tf32f(v.w);
            }
        }
        __syncthreads();
#pragma unroll
        for (int ks = 0; ks < 4; ks++) {
            int kk = ks * 8;
            unsigned a0 = __float_as_uint(Xs[row0 + g][kk + tg]);
            unsigned a1 = __float_as_uint(Xs[row0 + g + 8][kk + tg]);
            unsigned a2 = __float_as_uint(Xs[row0 + g][kk + tg + 4]);
            unsigned a3 = __float_as_uint(Xs[row0 + g + 8][kk + tg + 4]);
#pragma unroll
            for (int nt = 0; nt < 8; nt++) {
                unsigned b0 = __float_as_uint(Ws[kk + tg][nt * 8 + g]);
                unsigned b1 = __float_as_uint(Ws[kk + tg + 4][nt * 8 + g]);
                mma_tf32(d[nt], a0, a1, a2, a3, b0, b1);
            }
        }
        __syncthreads();
    }
#pragma unroll
    for (int nt = 0; nt < 8; nt++) {
        int c = nt * 8 + 2 * tg;
        int n1 = base + row0 + g;
        int n2 = n1 + 8;
        if (n1 < N_NODES) {
            *(float2*)&g_h2[(size_t)n1 * 64 + c] = make_float2(d[nt][0], d[nt][1]);
            __nv_bfloat162 p = __floats2bfloat162_rn(d[nt][0], d[nt][1]);
            *(unsigned*)&g_h2b[(size_t)n1 * 64 + c] = *(unsigned*)&p;
        }
        if (n2 < N_NODES) {
            *(float2*)&g_h2[(size_t)n2 * 64 + c] = make_float2(d[nt][2], d[nt][3]);
            __nv_bfloat162 p = __floats2bfloat162_rn(d[nt][2], d[nt][3]);
            *(unsigned*)&g_h2b[(size_t)n2 * 64 + c] = *(unsigned*)&p;
        }
    }
}

// ---------------- attention terms ----------------
__global__ void alpha1_kernel(const float* __restrict__ a_s,
                              const float* __restrict__ a_d) {
    int t = blockIdx.x * blockDim.x + threadIdx.x;
    if (t >= N_NODES * HEADS) return;
    int n = t >> 3, h = t & 7;
    const float* row = g_h1 + (size_t)n * HID + h * C1;
    float s = 0.0f, d = 0.0f;
#pragma unroll
    for (int c = 0; c < C1; c++) {
        float v = row[c];
        s += v * a_s[h * C1 + c];
        d += v * a_d[h * C1 + c];
    }
    g_as1[t] = s;
    g_ad1[t] = d;
}

__global__ void alpha2_kernel(const float* __restrict__ a_s,
                              const float* __restrict__ a_d) {
    int n = blockIdx.x * blockDim.x + threadIdx.x;
    if (n >= N_NODES) return;
    const float* row = g_h2 + (size_t)n * OUT_DIM;
    float s = 0.0f, d = 0.0f;
#pragma unroll
    for (int c = 0; c < OUT_DIM; c++) {
        float v = row[c];
        s += v * a_s[c];
        d += v * a_d[c];
    }
    g_as2[n] = s;
    g_ad2[n] = d;
}

// ---------------- CSR aggregation, layer 1 (16B gathers, 2 edges/step) -----
// Warp per node (uniform control flow -> full-mask shfl legal).
// Score phase: lane l -> (edge l>>3, head l&7), 4 edges per group.
// Gather phase: 2 steps; in step j half-warp `half` gathers edge 2j+half,
// each of its 16 lanes loading uint4 (8 bf16 = cols sl*8..+7).
__global__ void __launch_bounds__(256) agg1_csr_kernel(const float* __restrict__ b1) {
    const unsigned FULL = 0xffffffffu;
    int n = (blockIdx.x * blockDim.x + threadIdx.x) >> 5;
    int lane = threadIdx.x & 31;
    if (n >= N_NODES) return;
    int beg = g_off[n], end = g_off[n + 1];
    int h = lane & 7;          // score head
    int eslot = lane >> 3;     // score edge slot (0..3)
    int half = lane >> 4;      // gather half-warp (0/1)
    int sl = lane & 15;        // gather lane within half
    int ehead = sl >> 1;       // head owning cols sl*8..+7
    float ad = g_ad1[n * HEADS + h];
    float acc[8];
#pragma unroll
    for (int i = 0; i < 8; i++) acc[i] = 0.0f;
    float den = 0.0f;

    int cnt = end - beg;
    int nfull = cnt & ~3;
    int pfull = beg + nfull;

    for (int p = beg; p < pfull; p += 4) {
        int src = g_es[p + eslot];
        float sc = g_as1[src * HEADS + h] + ad;
        sc = (sc >= 0.0f) ? sc : NEG_SLOPE * sc;
        float e = expf(sc);
        den += e;
#pragma unroll
        for (int j = 0; j < 2; j++) {
            int k = 2 * j + half;
            int srcj = __shfl_sync(FULL, src, k * 8);
            float ej = __shfl_sync(FULL, e, k * 8 + ehead);
            uint4 raw = ((const uint4*)(g_h1b + (size_t)srcj * 128))[sl];
            float2 f0 = __bfloat1622float2(*(__nv_bfloat162*)&raw.x);
            float2 f1 = __bfloat1622float2(*(__nv_bfloat162*)&raw.y);
            float2 f2 = __bfloat1622float2(*(__nv_bfloat162*)&raw.z);
            float2 f3 = __bfloat1622float2(*(__nv_bfloat162*)&raw.w);
            acc[0] += f0.x * ej; acc[1] += f0.y * ej;
            acc[2] += f1.x * ej; acc[3] += f1.y * ej;
            acc[4] += f2.x * ej; acc[5] += f2.y * ej;
            acc[6] += f3.x * ej; acc[7] += f3.y * ej;
        }
    }
    int rem = cnt - nfull;     // 0..3, uniform across warp
    if (rem) {
        int eidx = pfull + eslot;
        int src = g_es[(eidx < end) ? eidx : beg];   // clamped -> safe load
        float sc = g_as1[src * HEADS + h] + ad;
        sc = (sc >= 0.0f) ? sc : NEG_SLOPE * sc;
        float e = (eslot < rem) ? expf(sc) : 0.0f;   // invalid edges weight 0
        den += e;
#pragma unroll
        for (int j = 0; j < 2; j++) {
            if (rem > 2 * j) {   // uniform condition
                int k = 2 * j + half;
                int srcj = __shfl_sync(FULL, src, k * 8);
                float ej = __shfl_sync(FULL, e, k * 8 + ehead);
                uint4 raw = ((const uint4*)(g_h1b + (size_t)srcj * 128))[sl];
                float2 f0 = __bfloat1622float2(*(__nv_bfloat162*)&raw.x);
                float2 f1 = __bfloat1622float2(*(__nv_bfloat162*)&raw.y);
                float2 f2 = __bfloat1622float2(*(__nv_bfloat162*)&raw.z);
                float2 f3 = __bfloat1622float2(*(__nv_bfloat162*)&raw.w);
                acc[0] += f0.x * ej; acc[1] += f0.y * ej;
                acc[2] += f1.x * ej; acc[3] += f1.y * ej;
                acc[4] += f2.x * ej; acc[5] += f2.y * ej;
                acc[6] += f3.x * ej; acc[7] += f3.y * ej;
            }
        }
    }
    den += __shfl_xor_sync(FULL, den, 8);
    den += __shfl_xor_sync(FULL, den, 16);
    float dh = __shfl_sync(FULL, den, ehead);   // lane h in 0..7 holds head h total
    // combine the two halves' partial sums (same cols, different edges)
#pragma unroll
    for (int i = 0; i < 8; i++) acc[i] += __shfl_xor_sync(FULL, acc[i], 16);
    float inv = 1.0f / dh;
    int cb = sl * 8 + half * 4;   // this lane writes 4 of the 8 combined cols
    float s0 = half ? acc[4] : acc[0];
    float s1 = half ? acc[5] : acc[1];
    float s2 = half ? acc[6] : acc[2];
    float s3 = half ? acc[7] : acc[3];
    const float4 bb = *(const float4*)&b1[cb];
    float4 r;
    r.x = s0 * inv + bb.x; r.y = s1 * inv + bb.y;
    r.z = s2 * inv + bb.z; r.w = s3 * inv + bb.w;
    r.x = (r.x > 0.f) ? r.x : expm1f(r.x);
    r.y = (r.y > 0.f) ? r.y : expm1f(r.y);
    r.z = (r.z > 0.f) ? r.z : expm1f(r.z);
    r.w = (r.w > 0.f) ? r.w : expm1f(r.w);
    *(float4*)&g_out1[(size_t)n * 128 + cb] = r;
}

// ---------------- CSR aggregation + log_softmax, layer 2 (16B gathers) -----
// Half-warp per node; half-warp-local masks (R5 lesson). Score: 16 edges per
// group, one per lane. Gather: 8 steps; step j has quarter q gathering edge
// 2j+q, each of its 8 lanes loading uint4 (cols s8*8..+7).
__global__ void __launch_bounds__(256) agg2_csr_kernel(const float* __restrict__ b2,
                                                       float* __restrict__ out) {
    int hw = (blockIdx.x * blockDim.x + threadIdx.x) >> 4;  // node id
    int lane = threadIdx.x & 31;
    int l = lane & 15;
    const unsigned mask = 0xffffu << (lane & 16);
    if (hw >= N_NODES) return;
    int n = hw;
    int beg = g_off[n], end = g_off[n + 1];
    float ad = g_ad2[n];
    int q = l >> 3;            // quarter within half-warp (0/1)
    int s8 = l & 7;            // lane within quarter
    float acc[8];
#pragma unroll
    for (int i = 0; i < 8; i++) acc[i] = 0.0f;
    float den = 0.0f;

    int cnt = end - beg;
    int nfull = cnt & ~15;
    int pfull = beg + nfull;

    for (int p = beg; p < pfull; p += 16) {
        int src = g_es[p + l];
        float sc = g_as2[src] + ad;
        sc = (sc >= 0.0f) ? sc : NEG_SLOPE * sc;
        float e = expf(sc);
        den += e;
#pragma unroll
        for (int j = 0; j < 8; j++) {
            int k = 2 * j + q;
            int srcj = __shfl_sync(mask, src, k, 16);
            float ej = __shfl_sync(mask, e, k, 16);
            uint4 raw = ((const uint4*)(g_h2b + (size_t)srcj * 64))[s8];
            float2 f0 = __bfloat1622float2(*(__nv_bfloat162*)&raw.x);
            float2 f1 = __bfloat1622float2(*(__nv_bfloat162*)&raw.y);
            float2 f2 = __bfloat1622float2(*(__nv_bfloat162*)&raw.z);
            float2 f3 = __bfloat1622float2(*(__nv_bfloat162*)&raw.w);
            acc[0] += f0.x * ej; acc[1] += f0.y * ej;
            acc[2] += f1.x * ej; acc[3] += f1.y * ej;
            acc[4] += f2.x * ej; acc[5] += f2.y * ej;
            acc[6] += f3.x * ej; acc[7] += f3.y * ej;
        }
    }
    int rem = cnt - nfull;   // 0..15, uniform across half-warp
    if (rem) {
        int eidx = pfull + l;
        int src = g_es[(eidx < end) ? eidx : beg];
        float sc = g_as2[src] + ad;
        sc = (sc >= 0.0f) ? sc : NEG_SLOPE * sc;
        float e = (l < rem) ? expf(sc) : 0.0f;
        den += e;
#pragma unroll
        for (int j = 0; j < 8; j++) {
            if (rem > 2 * j) {   // uniform within half-warp
                int k = 2 * j + q;
                int srcj = __shfl_sync(mask, src, k, 16);
                float ej = __shfl_sync(mask, e, k, 16);
                uint4 raw = ((const uint4*)(g_h2b + (size_t)srcj * 64))[s8];
                float2 f0 = __bfloat1622float2(*(__nv_bfloat162*)&raw.x);
                float2 f1 = __bfloat1622float2(*(__nv_bfloat162*)&raw.y);
                float2 f2 = __bfloat1622float2(*(__nv_bfloat162*)&raw.z);
                float2 f3 = __bfloat1622float2(*(__nv_bfloat162*)&raw.w);
                acc[0] += f0.x * ej; acc[1] += f0.y * ej;
                acc[2] += f1.x * ej; acc[3] += f1.y * ej;
                acc[4] += f2.x * ej; acc[5] += f2.y * ej;
                acc[6] += f3.x * ej; acc[7] += f3.y * ej;
            }
        }
    }
#pragma unroll
    for (int o = 8; o; o >>= 1) den += __shfl_xor_sync(mask, den, o, 16);
    // combine quarters (same cols, different edges)
#pragma unroll
    for (int i = 0; i < 8; i++) acc[i] += __shfl_xor_sync(mask, acc[i], 8, 16);
    float inv = 1.0f / den;
    float v[8];
    const float4 bb0 = *(const float4*)&b2[s8 * 8];
    const float4 bb1 = *(const float4*)&b2[s8 * 8 + 4];
    v[0] = acc[0] * inv + bb0.x; v[1] = acc[1] * inv + bb0.y;
    v[2] = acc[2] * inv + bb0.z; v[3] = acc[3] * inv + bb0.w;
    v[4] = acc[4] * inv + bb1.x; v[5] = acc[5] * inv + bb1.y;
    v[6] = acc[6] * inv + bb1.z; v[7] = acc[7] * inv + bb1.w;
    // log_softmax over 64 values (8 distinct lanes x 8, duplicated across q)
    float m = v[0];
#pragma unroll
    for (int i = 1; i < 8; i++) m = fmaxf(m, v[i]);
#pragma unroll
    for (int o = 4; o; o >>= 1) m = fmaxf(m, __shfl_xor_sync(mask, m, o, 16));
    float s = 0.0f;
#pragma unroll
    for (int i = 0; i < 8; i++) s += expf(v[i] - m);
#pragma unroll
    for (int o = 4; o; o >>= 1) s += __shfl_xor_sync(mask, s, o, 16);
    float lse = m + logf(s);
    float o0 = (q ? v[4] : v[0]) - lse;
    float o1 = (q ? v[5] : v[1]) - lse;
    float o2 = (q ? v[6] : v[2]) - lse;
    float o3 = (q ? v[7] : v[3]) - lse;
    *(float4*)&out[(size_t)n * 64 + s8 * 8 + q * 4] = make_float4(o0, o1, o2, o3);
}

// ---------------- launch ----------------
extern "C" void kernel_launch(void* const* d_in, const int* in_sizes, int n_in,
                              void* d_out, int out_size) {
    const float* x   = (const float*)d_in[0];
    const void*  ei  = d_in[1];
    const float* W1  = (const float*)d_in[2];
    const float* as1 = (const float*)d_in[3];
    const float* ad1 = (const float*)d_in[4];
    const float* b1  = (const float*)d_in[5];
    const float* W2  = (const float*)d_in[6];
    const float* as2 = (const float*)d_in[7];
    const float* ad2 = (const float*)d_in[8];
    const float* b2  = (const float*)d_in[9];
    float* out = (float*)d_out;

    // ---- fork: CSR build on side stream, concurrent with gemm1/alpha1 ----
    cudaStream_t sb = g_aux.ok ? g_aux.s2 : 0;
    if (g_aux.ok) {
        cudaEventRecord(g_aux.fork, 0);
        cudaStreamWaitEvent(g_aux.s2, g_aux.fork, 0);
    }
    detect_kernel<<<1, 1024, 0, sb>>>((const unsigned long long*)ei);
    zerocnt_kernel<<<(N_NODES + 255) / 256, 256, 0, sb>>>();
    convert_hist_kernel<<<(ET + 255) / 256, 256, 0, sb>>>(ei);
    scan_local_kernel<<<NB_SCAN, 1024, 0, sb>>>();
    scan_bsum_kernel<<<1, 64, 0, sb>>>();
    addoff_kernel<<<(N_NODES + 255) / 256, 256, 0, sb>>>();
    scatter_kernel<<<(ET + 255) / 256, 256, 0, sb>>>();
    if (g_aux.ok) cudaEventRecord(g_aux.join, g_aux.s2);

    // ---- main stream: layer-1 dense work (independent of CSR) ----
    gemm1_kernel<<<(N_NODES + 127) / 128, 256>>>(x, W1);
    alpha1_kernel<<<(N_NODES * HEADS + 255) / 256, 256>>>(as1, ad1);

    // ---- join: aggregation needs the CSR ----
    if (g_aux.ok) cudaStreamWaitEvent(0, g_aux.join, 0);
    agg1_csr_kernel<<<(N_NODES * 32 + 255) / 256, 256>>>(b1);

    // ---- layer 2 ----
    gemm2_kernel<<<(N_NODES + 127) / 128, 256>>>(W2);
    alpha2_kernel<<<(N_NODES + 255) / 256, 256>>>(as2, ad2);
    agg2_csr_kernel<<<(N_NODES * 16 + 255) / 256, 256>>>(b2, out);
}

// round 13
// speedup vs baseline: 1.4222x; 1.4222x over previous
#include <cuda_runtime.h>
#include <cuda_bf16.h>
#include <math.h>

#define N_NODES 50000
#define E_EDGES 800000
#define ET (E_EDGES + N_NODES)   /* 850000 edges incl. self loops */
#define HID 128
#define HEADS 8
#define C1 16
#define OUT_DIM 64
#define NEG_SLOPE 0.2f
#define NB_SCAN ((N_NODES + 1023) / 1024)   /* 49 scan tiles */

// ---------------- scratch (device globals; no allocation) ----------------
__device__ __align__(16) float g_h1[N_NODES * HID];    // layer1 projection (fp32, for scores)
__device__ __align__(16) __nv_bfloat16 g_h1b[N_NODES * HID];   // bf16 copy (gather payload)
__device__ __align__(16) float g_out1[N_NODES * HID];  // layer1 output (post-ELU)
__device__ __align__(16) float g_h2[N_NODES * OUT_DIM];
__device__ __align__(16) __nv_bfloat16 g_h2b[N_NODES * OUT_DIM];
__device__ float g_as1[N_NODES * HEADS];
__device__ float g_ad1[N_NODES * HEADS];
__device__ float g_as2[N_NODES];
__device__ float g_ad2[N_NODES];
__device__ int   g_es[ET];          // src ids sorted by dst (CSR values)
__device__ int   g_cnt[N_NODES];
__device__ int   g_off[N_NODES + 1];
__device__ int   g_cur[N_NODES];
__device__ int   g_bsum[NB_SCAN];
__device__ int   g_boff[NB_SCAN];
__device__ int   g_is64;

// ---------------- side stream for CSR-build / GEMM overlap ----------------
namespace {
struct AuxStreams {
    cudaStream_t s2 = 0;
    cudaEvent_t  fork = 0, join = 0;
    bool ok = false;
    AuxStreams() {
        if (cudaStreamCreateWithFlags(&s2, cudaStreamNonBlocking) == cudaSuccess &&
            cudaEventCreateWithFlags(&fork, cudaEventDisableTiming) == cudaSuccess &&
            cudaEventCreateWithFlags(&join, cudaEventDisableTiming) == cudaSuccess) {
            ok = true;
        } else {
            s2 = 0;
            ok = false;
        }
    }
};
AuxStreams g_aux;
}

// ---------------- tf32 helpers ----------------
__device__ __forceinline__ float f2tf32f(float f) {
    unsigned r;
    asm("cvt.rna.tf32.f32 %0, %1;" : "=r"(r) : "f"(f));
    return __uint_as_float(r);
}
__device__ __forceinline__ void mma_tf32(float* d, unsigned a0, unsigned a1,
                                         unsigned a2, unsigned a3,
                                         unsigned b0, unsigned b1) {
    asm volatile(
        "mma.sync.aligned.m16n8k8.row.col.f32.tf32.tf32.f32 "
        "{%0,%1,%2,%3}, {%4,%5,%6,%7}, {%8,%9}, {%0,%1,%2,%3};"
        : "+f"(d[0]), "+f"(d[1]), "+f"(d[2]), "+f"(d[3])
        : "r"(a0), "r"(a1), "r"(a2), "r"(a3), "r"(b0), "r"(b1));
}

// ---------------- edge decode helpers ----------------
__device__ __forceinline__ void decode_edge(const void* ei, int t, int& s, int& d) {
    if (t >= E_EDGES) {
        s = d = t - E_EDGES;       // self loop
    } else if (g_is64) {
        const long long* p = (const long long*)ei;
        s = (int)p[t];
        d = (int)p[E_EDGES + t];
    } else {
        const int* p = (const int*)ei;
        s = p[t];
        d = p[E_EDGES + t];
    }
}

// ---------------- edge dtype detection ----------------
__global__ void detect_kernel(const unsigned long long* __restrict__ e64) {
    __shared__ int bad;
    if (threadIdx.x == 0) bad = 0;
    __syncthreads();
    unsigned long long v = e64[threadIdx.x];  // blockDim.x = 1024
    if (v >= (unsigned long long)N_NODES) atomicOr(&bad, 1);
    __syncthreads();
    if (threadIdx.x == 0) g_is64 = bad ? 0 : 1;
}

__global__ void zerocnt_kernel() {
    int i = blockIdx.x * blockDim.x + threadIdx.x;
    if (i < N_NODES) g_cnt[i] = 0;
}

// decode edges (+self loops) and histogram destinations (no staging stores)
__global__ void convert_hist_kernel(const void* __restrict__ ei) {
    int t = blockIdx.x * blockDim.x + threadIdx.x;
    if (t >= ET) return;
    int s, d;
    decode_edge(ei, t, s, d);
    atomicAdd(&g_cnt[d], 1);
}

// ---------------- chip-wide 3-phase exclusive scan of g_cnt ----------------
__global__ void scan_local_kernel() {
    __shared__ int sh[1024];
    int t = threadIdx.x;
    int i = blockIdx.x * 1024 + t;
    int v = (i < N_NODES) ? g_cnt[i] : 0;
    sh[t] = v;
    __syncthreads();
    for (int o = 1; o < 1024; o <<= 1) {
        int cur = sh[t];
        int idx = (t >= o) ? (t - o) : 0;   // always valid (no speculative OOB LDS)
        int u = sh[idx];
        u = (t >= o) ? u : 0;
        __syncthreads();
        sh[t] = cur + u;
        __syncthreads();
    }
    if (i < N_NODES) g_off[i] = sh[t] - v;  // exclusive within tile
    if (t == 1023) g_bsum[blockIdx.x] = sh[1023];
}

__global__ void scan_bsum_kernel() {
    __shared__ int sh[64];
    int t = threadIdx.x;   // blockDim.x = 64 >= NB_SCAN
    int v = (t < NB_SCAN) ? g_bsum[t] : 0;
    sh[t] = v;
    __syncthreads();
    for (int o = 1; o < 64; o <<= 1) {
        int cur = sh[t];
        int idx = (t >= o) ? (t - o) : 0;
        int u = sh[idx];
        u = (t >= o) ? u : 0;
        __syncthreads();
        sh[t] = cur + u;
        __syncthreads();
    }
    if (t < NB_SCAN) g_boff[t] = sh[t] - v;  // exclusive
}

__global__ void addoff_kernel() {
    int i = blockIdx.x * blockDim.x + threadIdx.x;
    if (i < N_NODES) {
        int o = g_off[i] + g_boff[i >> 10];
        g_off[i] = o;
        g_cur[i] = o;
    }
    if (i == 0) g_off[N_NODES] = ET;
}

__global__ void scatter_kernel(const void* __restrict__ ei) {
    int t = blockIdx.x * blockDim.x + threadIdx.x;
    if (t >= ET) return;
    int s, d;
    decode_edge(ei, t, s, d);
    int pos = atomicAdd(&g_cur[d], 1);
    g_es[pos] = s;
}

// ---------------- tf32 tensor-core GEMM, layer 1 (128x128 tile) ------------
__global__ void __launch_bounds__(256) gemm1_kernel(const float* __restrict__ X,
                                                    const float* __restrict__ W) {
    __shared__ float Xs[128][36];   // pad 36: A-frag bank = (4g+tg), conflict-free
    __shared__ float Ws[32][136];   // pad 136: B-frag bank = (8tg+g), conflict-free
    const int tid = threadIdx.x;
    const int warp = tid >> 5, lane = tid & 31;
    const int g = lane >> 2, tg = lane & 3;
    const int base = blockIdx.x * 128;
    const int row0 = warp * 16;

    float d[16][4];
#pragma unroll
    for (int nt = 0; nt < 16; nt++)
#pragma unroll
        for (int j = 0; j < 4; j++) d[nt][j] = 0.0f;

    const int lr = tid >> 1, lh = tid & 1;   // X loader
    const int kw = tid >> 3, seg = tid & 7;  // W loader

    for (int k0 = 0; k0 < 128; k0 += 32) {
        {
            int node = base + lr; if (node >= N_NODES) node = N_NODES - 1;
            const float4* xr = (const float4*)(X + (size_t)node * 128 + k0 + lh * 16);
#pragma unroll
            for (int c = 0; c < 4; c++) {
                float4 v = xr[c];
                int kk = lh * 16 + c * 4;
                Xs[lr][kk + 0] = f2tf32f(v.x); Xs[lr][kk + 1] = f2tf32f(v.y);
                Xs[lr][kk + 2] = f2tf32f(v.z); Xs[lr][kk + 3] = f2tf32f(v.w);
            }
        }
        {
            const float4* wr = (const float4*)(W + (size_t)(k0 + kw) * 128 + seg * 16);
#pragma unroll
            for (int c = 0; c < 4; c++) {
                float4 v = wr[c];
                int cc = seg * 16 + c * 4;
                Ws[kw][cc + 0] = f2tf32f(v.x); Ws[kw][cc + 1] = f2tf32f(v.y);
                Ws[kw][cc + 2] = f2tf32f(v.z); Ws[kw][cc + 3] = f2tf32f(v.w);
            }
        }
        __syncthreads();
#pragma unroll
        for (int ks = 0; ks < 4; ks++) {
            int kk = ks * 8;
            unsigned a0 = __float_as_uint(Xs[row0 + g][kk + tg]);
            unsigned a1 = __float_as_uint(Xs[row0 + g + 8][kk + tg]);
            unsigned a2 = __float_as_uint(Xs[row0 + g][kk + tg + 4]);
            unsigned a3 = __float_as_uint(Xs[row0 + g + 8][kk + tg + 4]);
#pragma unroll
            for (int nt = 0; nt < 16; nt++) {
                unsigned b0 = __float_as_uint(Ws[kk + tg][nt * 8 + g]);
                unsigned b1 = __float_as_uint(Ws[kk + tg + 4][nt * 8 + g]);
                mma_tf32(d[nt], a0, a1, a2, a3, b0, b1);
            }
        }
        __syncthreads();
    }
#pragma unroll
    for (int nt = 0; nt < 16; nt++) {
        int c = nt * 8 + 2 * tg;
        int n1 = base + row0 + g;
        int n2 = n1 + 8;
        if (n1 < N_NODES) {
            *(float2*)&g_h1[(size_t)n1 * 128 + c] = make_float2(d[nt][0], d[nt][1]);
            __nv_bfloat162 p = __floats2bfloat162_rn(d[nt][0], d[nt][1]);
            *(unsigned*)&g_h1b[(size_t)n1 * 128 + c] = *(unsigned*)&p;
        }
        if (n2 < N_NODES) {
            *(float2*)&g_h1[(size_t)n2 * 128 + c] = make_float2(d[nt][2], d[nt][3]);
            __nv_bfloat162 p = __floats2bfloat162_rn(d[nt][2], d[nt][3]);
            *(unsigned*)&g_h1b[(size_t)n2 * 128 + c] = *(unsigned*)&p;
        }
    }
}

// ---------------- tf32 tensor-core GEMM, layer 2 (128x64 tile) -------------
__global__ void __launch_bounds__(256) gemm2_kernel(const float* __restrict__ W) {
    __shared__ float Xs[128][36];
    __shared__ float Ws[32][72];    // pad 72: B-frag bank = (8tg+g), conflict-free
    const int tid = threadIdx.x;
    const int warp = tid >> 5, lane = tid & 31;
    const int g = lane >> 2, tg = lane & 3;
    const int base = blockIdx.x * 128;
    const int row0 = warp * 16;

    float d[8][4];
#pragma unroll
    for (int nt = 0; nt < 8; nt++)
#pragma unroll
        for (int j = 0; j < 4; j++) d[nt][j] = 0.0f;

    const int lr = tid >> 1, lh = tid & 1;   // X loader
    const int kw = tid >> 3, seg = tid & 7;  // W loader

    for (int k0 = 0; k0 < 128; k0 += 32) {
        {
            int node = base + lr; if (node >= N_NODES) node = N_NODES - 1;
            const float4* xr = (const float4*)(g_out1 + (size_t)node * 128 + k0 + lh * 16);
#pragma unroll
            for (int c = 0; c < 4; c++) {
                float4 v = xr[c];
                int kk = lh * 16 + c * 4;
                Xs[lr][kk + 0] = f2tf32f(v.x); Xs[lr][kk + 1] = f2tf32f(v.y);
                Xs[lr][kk + 2] = f2tf32f(v.z); Xs[lr][kk + 3] = f2tf32f(v.w);
            }
        }
        {
            const float4* wr = (const float4*)(W + (size_t)(k0 + kw) * 64 + seg * 8);
#pragma unroll
            for (int c = 0; c < 2; c++) {
                float4 v = wr[c];
                int cc = seg * 8 + c * 4;
                Ws[kw][cc + 0] = f2tf32f(v.x); Ws[kw][cc + 1] = f2tf32f(v.y);
                Ws[kw][cc + 2] = f2tf32f(v.z); Ws[kw][cc + 3] = f2tf32f(v.w);
            }
        }
        __syncthreads();
#pragma unroll
        for (int ks = 0; ks < 4; ks++) {
            int kk = ks * 8;
            unsigned a0 = __float_as_uint(Xs[row0 + g][kk + tg]);
            unsigned a1 = __float_as_uint(Xs[row0 + g + 8][kk + tg]);
            unsigned a2 = __float_as_uint(Xs[row0 + g][kk + tg + 4]);
            unsigned a3 = __float_as_uint(Xs[row0 + g + 8][kk + tg + 4]);
#pragma unroll
            for (int nt = 0; nt < 8; nt++) {
                unsigned b0 = __float_as_uint(Ws[kk + tg][nt * 8 + g]);
                unsigned b1 = __float_as_uint(Ws[kk + tg + 4][nt * 8 + g]);
                mma_tf32(d[nt], a0, a1, a2, a3, b0, b1);
            }
        }
        __syncthreads();
    }
#pragma unroll
    for (int nt = 0; nt < 8; nt++) {
        int c = nt * 8 + 2 * tg;
        int n1 = base + row0 + g;
        int n2 = n1 + 8;
        if (n1 < N_NODES) {
            *(float2*)&g_h2[(size_t)n1 * 64 + c] = make_float2(d[nt][0], d[nt][1]);
            __nv_bfloat162 p = __floats2bfloat162_rn(d[nt][0], d[nt][1]);
            *(unsigned*)&g_h2b[(size_t)n1 * 64 + c] = *(unsigned*)&p;
        }
        if (n2 < N_NODES) {
            *(float2*)&g_h2[(size_t)n2 * 64 + c] = make_float2(d[nt][2], d[nt][3]);
            __nv_bfloat162 p = __floats2bfloat162_rn(d[nt][2], d[nt][3]);
            *(unsigned*)&g_h2b[(size_t)n2 * 64 + c] = *(unsigned*)&p;
        }
    }
}

// ---------------- attention terms ----------------
__global__ void alpha1_kernel(const float* __restrict__ a_s,
                              const float* __restrict__ a_d) {
    int t = blockIdx.x * blockDim.x + threadIdx.x;
    if (t >= N_NODES * HEADS) return;
    int n = t >> 3, h = t & 7;
    const float* row = g_h1 + (size_t)n * HID + h * C1;
    float s = 0.0f, d = 0.0f;
#pragma unroll
    for (int c = 0; c < C1; c++) {
        float v = row[c];
        s += v * a_s[h * C1 + c];
        d += v * a_d[h * C1 + c];
    }
    g_as1[t] = s;
    g_ad1[t] = d;
}

__global__ void alpha2_kernel(const float* __restrict__ a_s,
                              const float* __restrict__ a_d) {
    int n = blockIdx.x * blockDim.x + threadIdx.x;
    if (n >= N_NODES) return;
    const float* row = g_h2 + (size_t)n * OUT_DIM;
    float s = 0.0f, d = 0.0f;
#pragma unroll
    for (int c = 0; c < OUT_DIM; c++) {
        float v = row[c];
        s += v * a_s[c];
        d += v * a_d[c];
    }
    g_as2[n] = s;
    g_ad2[n] = d;
}

// ---------------- CSR aggregation, layer 1 (R11 form: bf16 8B gathers) -----
__global__ void __launch_bounds__(256) agg1_csr_kernel(const float* __restrict__ b1) {
    const unsigned FULL = 0xffffffffu;
    int n = (blockIdx.x * blockDim.x + threadIdx.x) >> 5;
    int lane = threadIdx.x & 31;
    if (n >= N_NODES) return;
    int beg = g_off[n], end = g_off[n + 1];
    int h = lane & 7;          // head for score phase
    int eslot = lane >> 3;     // 0..3: which edge of the group
    float ad = g_ad1[n * HEADS + h];
    float4 acc = make_float4(0.f, 0.f, 0.f, 0.f);
    float den = 0.0f;

    int cnt = end - beg;
    int nfull = cnt & ~3;
    int pfull = beg + nfull;

    for (int p = beg; p < pfull; p += 4) {
        int src = g_es[p + eslot];
        float sc = g_as1[src * HEADS + h] + ad;
        sc = (sc >= 0.0f) ? sc : NEG_SLOPE * sc;
        float e = expf(sc);
        den += e;
#pragma unroll
        for (int j = 0; j < 4; j++) {
            int srcj = __shfl_sync(FULL, src, j * 8);
            float ej = __shfl_sync(FULL, e, j * 8 + (lane >> 2));
            uint2 raw = ((const uint2*)(g_h1b + (size_t)srcj * 128))[lane];
            float2 f0 = __bfloat1622float2(*(__nv_bfloat162*)&raw.x);
            float2 f1 = __bfloat1622float2(*(__nv_bfloat162*)&raw.y);
            acc.x += f0.x * ej; acc.y += f0.y * ej;
            acc.z += f1.x * ej; acc.w += f1.y * ej;
        }
    }
    int rem = cnt - nfull;     // 0..3, uniform across warp
    if (rem) {
        int eidx = pfull + eslot;
        int src = g_es[(eidx < end) ? eidx : beg];
        float sc = g_as1[src * HEADS + h] + ad;
        sc = (sc >= 0.0f) ? sc : NEG_SLOPE * sc;
        float e = (eslot < rem) ? expf(sc) : 0.0f;
        den += e;
        for (int j = 0; j < rem; j++) {
            int srcj = __shfl_sync(FULL, src, j * 8);
            float ej = __shfl_sync(FULL, e, j * 8 + (lane >> 2));
            uint2 raw = ((const uint2*)(g_h1b + (size_t)srcj * 128))[lane];
            float2 f0 = __bfloat1622float2(*(__nv_bfloat162*)&raw.x);
            float2 f1 = __bfloat1622float2(*(__nv_bfloat162*)&raw.y);
            acc.x += f0.x * ej; acc.y += f0.y * ej;
            acc.z += f1.x * ej; acc.w += f1.y * ej;
        }
    }
    den += __shfl_xor_sync(FULL, den, 8);
    den += __shfl_xor_sync(FULL, den, 16);
    float dh = __shfl_sync(FULL, den, lane >> 2);
    float inv = 1.0f / dh;
    const float4 bb = ((const float4*)b1)[lane];
    float4 r;
    r.x = acc.x * inv + bb.x; r.y = acc.y * inv + bb.y;
    r.z = acc.z * inv + bb.z; r.w = acc.w * inv + bb.w;
    r.x = (r.x > 0.f) ? r.x : expm1f(r.x);
    r.y = (r.y > 0.f) ? r.y : expm1f(r.y);
    r.z = (r.z > 0.f) ? r.z : expm1f(r.z);
    r.w = (r.w > 0.f) ? r.w : expm1f(r.w);
    ((float4*)(g_out1 + (size_t)n * 128))[lane] = r;
}

// ---------------- CSR aggregation + log_softmax, layer 2 (R11 form) --------
__global__ void __launch_bounds__(256) agg2_csr_kernel(const float* __restrict__ b2,
                                                       float* __restrict__ out) {
    int hw = (blockIdx.x * blockDim.x + threadIdx.x) >> 4;  // node id
    int lane = threadIdx.x & 31;
    int l = lane & 15;
    const unsigned mask = 0xffffu << (lane & 16);  // own half-warp only (R5 lesson)
    if (hw >= N_NODES) return;
    int n = hw;
    int beg = g_off[n], end = g_off[n + 1];
    float ad = g_ad2[n];
    float4 acc = make_float4(0.f, 0.f, 0.f, 0.f);
    float den = 0.0f;

    int cnt = end - beg;
    int nfull = cnt & ~15;
    int pfull = beg + nfull;

    for (int p = beg; p < pfull; p += 16) {
        int src = g_es[p + l];
        float sc = g_as2[src] + ad;
        sc = (sc >= 0.0f) ? sc : NEG_SLOPE * sc;
        float e = expf(sc);
        den += e;
#pragma unroll
        for (int j = 0; j < 16; j++) {
            int srcj = __shfl_sync(mask, src, j, 16);
            float ej = __shfl_sync(mask, e, j, 16);
            uint2 raw = ((const uint2*)(g_h2b + (size_t)srcj * 64))[l];
            float2 f0 = __bfloat1622float2(*(__nv_bfloat162*)&raw.x);
            float2 f1 = __bfloat1622float2(*(__nv_bfloat162*)&raw.y);
            acc.x += f0.x * ej; acc.y += f0.y * ej;
            acc.z += f1.x * ej; acc.w += f1.y * ej;
        }
    }
    int rem = cnt - nfull;   // 0..15, uniform across half-warp
    if (rem) {
        int eidx = pfull + l;
        int src = g_es[(eidx < end) ? eidx : beg];
        float sc = g_as2[src] + ad;
        sc = (sc >= 0.0f) ? sc : NEG_SLOPE * sc;
        float e = (l < rem) ? expf(sc) : 0.0f;
        den += e;
        for (int j = 0; j < rem; j++) {
            int srcj = __shfl_sync(mask, src, j, 16);
            float ej = __shfl_sync(mask, e, j, 16);
            uint2 raw = ((const uint2*)(g_h2b + (size_t)srcj * 64))[l];
            float2 f0 = __bfloat1622float2(*(__nv_bfloat162*)&raw.x);
            float2 f1 = __bfloat1622float2(*(__nv_bfloat162*)&raw.y);
            acc.x += f0.x * ej; acc.y += f0.y * ej;
            acc.z += f1.x * ej; acc.w += f1.y * ej;
        }
    }
#pragma unroll
    for (int o = 8; o; o >>= 1) den += __shfl_xor_sync(mask, den, o, 16);
    float inv = 1.0f / den;
    const float4 bb = ((const float4*)b2)[l];
    float v[4];
    v[0] = acc.x * inv + bb.x; v[1] = acc.y * inv + bb.y;
    v[2] = acc.z * inv + bb.z; v[3] = acc.w * inv + bb.w;
    float m = fmaxf(fmaxf(v[0], v[1]), fmaxf(v[2], v[3]));
#pragma unroll
    for (int o = 8; o; o >>= 1) m = fmaxf(m, __shfl_xor_sync(mask, m, o, 16));
    float s = expf(v[0] - m) + expf(v[1] - m) + expf(v[2] - m) + expf(v[3] - m);
#pragma unroll
    for (int o = 8; o; o >>= 1) s += __shfl_xor_sync(mask, s, o, 16);
    float lse = m + logf(s);
    ((float4*)(out + (size_t)n * 64))[l] =
        make_float4(v[0] - lse, v[1] - lse, v[2] - lse, v[3] - lse);
}

// ---------------- launch ----------------
extern "C" void kernel_launch(void* const* d_in, const int* in_sizes, int n_in,
                              void* d_out, int out_size) {
    const float* x   = (const float*)d_in[0];
    const void*  ei  = d_in[1];
    const float* W1  = (const float*)d_in[2];
    const float* as1 = (const float*)d_in[3];
    const float* ad1 = (const float*)d_in[4];
    const float* b1  = (const float*)d_in[5];
    const float* W2  = (const float*)d_in[6];
    const float* as2 = (const float*)d_in[7];
    const float* ad2 = (const float*)d_in[8];
    const float* b2  = (const float*)d_in[9];
    float* out = (float*)d_out;

    // ---- fork: CSR build on side stream, concurrent with gemm1/alpha1 ----
    cudaStream_t sb = g_aux.ok ? g_aux.s2 : 0;
    if (g_aux.ok) {
        cudaEventRecord(g_aux.fork, 0);
        cudaStreamWaitEvent(g_aux.s2, g_aux.fork, 0);
    }
    detect_kernel<<<1, 1024, 0, sb>>>((const unsigned long long*)ei);
    zerocnt_kernel<<<(N_NODES + 255) / 256, 256, 0, sb>>>();
    convert_hist_kernel<<<(ET + 255) / 256, 256, 0, sb>>>(ei);
    scan_local_kernel<<<NB_SCAN, 1024, 0, sb>>>();
    scan_bsum_kernel<<<1, 64, 0, sb>>>();
    addoff_kernel<<<(N_NODES + 255) / 256, 256, 0, sb>>>();
    scatter_kernel<<<(ET + 255) / 256, 256, 0, sb>>>(ei);
    if (g_aux.ok) cudaEventRecord(g_aux.join, g_aux.s2);

    // ---- main stream: layer-1 dense work (independent of CSR) ----
    gemm1_kernel<<<(N_NODES + 127) / 128, 256>>>(x, W1);
    alpha1_kernel<<<(N_NODES * HEADS + 255) / 256, 256>>>(as1, ad1);

    // ---- join: aggregation needs the CSR ----
    if (g_aux.ok) cudaStreamWaitEvent(0, g_aux.join, 0);
    agg1_csr_kernel<<<(N_NODES * 32 + 255) / 256, 256>>>(b1);

    // ---- layer 2 ----
    gemm2_kernel<<<(N_NODES + 127) / 128, 256>>>(W2);
    alpha2_kernel<<<(N_NODES + 255) / 256, 256>>>(as2, ad2);
    agg2_csr_kernel<<<(N_NODES * 16 + 255) / 256, 256>>>(b2, out);
}

// round 14
// speedup vs baseline: 1.4511x; 1.0204x over previous
#include <cuda_runtime.h>
#include <cuda_bf16.h>
#include <math.h>

#define N_NODES 50000
#define E_EDGES 800000
#define ET (E_EDGES + N_NODES)   /* 850000 edges incl. self loops */
#define HID 128
#define HEADS 8
#define C1 16
#define OUT_DIM 64
#define NEG_SLOPE 0.2f
#define NB_SCAN ((N_NODES + 1023) / 1024)   /* 49 scan tiles */

// ---------------- scratch (device globals; no allocation) ----------------
__device__ __align__(16) float g_h1[N_NODES * HID];    // layer1 projection (fp32, for scores)
__device__ __align__(16) __nv_bfloat16 g_h1b[N_NODES * HID];   // bf16 copy (gather payload)
__device__ __align__(16) float g_out1[N_NODES * HID];  // layer1 output (post-ELU)
__device__ __align__(16) float g_h2[N_NODES * OUT_DIM];
__device__ __align__(16) __nv_bfloat16 g_h2b[N_NODES * OUT_DIM];
__device__ float g_as1[N_NODES * HEADS];
__device__ float g_ad1[N_NODES * HEADS];
__device__ float g_as2[N_NODES];
__device__ float g_ad2[N_NODES];
__device__ int   g_src[ET];
__device__ int   g_dst[ET];
__device__ int   g_es[ET];          // src ids sorted by dst (CSR values)
__device__ int   g_cnt[N_NODES];    // zero at call entry (scan_local re-zeroes)
__device__ int   g_off[N_NODES + 1];
__device__ int   g_cur[N_NODES];
__device__ int   g_bsum[NB_SCAN];
__device__ int   g_boff[NB_SCAN];
__device__ int   g_is64;

// ---------------- side stream for CSR-build / GEMM overlap ----------------
namespace {
struct AuxStreams {
    cudaStream_t s2 = 0;
    cudaEvent_t  fork = 0, join = 0;
    bool ok = false;
    AuxStreams() {
        if (cudaStreamCreateWithFlags(&s2, cudaStreamNonBlocking) == cudaSuccess &&
            cudaEventCreateWithFlags(&fork, cudaEventDisableTiming) == cudaSuccess &&
            cudaEventCreateWithFlags(&join, cudaEventDisableTiming) == cudaSuccess) {
            ok = true;
        } else {
            s2 = 0;
            ok = false;
        }
    }
};
AuxStreams g_aux;
}

// ---------------- tf32 helpers ----------------
__device__ __forceinline__ float f2tf32f(float f) {
    unsigned r;
    asm("cvt.rna.tf32.f32 %0, %1;" : "=r"(r) : "f"(f));
    return __uint_as_float(r);
}
__device__ __forceinline__ void mma_tf32(float* d, unsigned a0, unsigned a1,
                                         unsigned a2, unsigned a3,
                                         unsigned b0, unsigned b1) {
    asm volatile(
        "mma.sync.aligned.m16n8k8.row.col.f32.tf32.tf32.f32 "
        "{%0,%1,%2,%3}, {%4,%5,%6,%7}, {%8,%9}, {%0,%1,%2,%3};"
        : "+f"(d[0]), "+f"(d[1]), "+f"(d[2]), "+f"(d[3])
        : "r"(a0), "r"(a1), "r"(a2), "r"(a3), "r"(b0), "r"(b1));
}

// ---------------- edge dtype detection ----------------
__global__ void detect_kernel(const unsigned long long* __restrict__ e64) {
    __shared__ int bad;
    if (threadIdx.x == 0) bad = 0;
    __syncthreads();
    unsigned long long v = e64[threadIdx.x];  // blockDim.x = 1024
    if (v >= (unsigned long long)N_NODES) atomicOr(&bad, 1);
    __syncthreads();
    if (threadIdx.x == 0) g_is64 = bad ? 0 : 1;
}

// decode edges (+self loops), stage src/dst, histogram destinations.
// g_cnt is zero on entry (device globals start zeroed; scan_local re-zeroes).
__global__ void convert_hist_kernel(const void* __restrict__ ei) {
    int t = blockIdx.x * blockDim.x + threadIdx.x;
    if (t >= ET) return;
    int s, d;
    if (t >= E_EDGES) {
        s = d = t - E_EDGES;
    } else if (g_is64) {
        const long long* p = (const long long*)ei;
        s = (int)p[t];
        d = (int)p[E_EDGES + t];
    } else {
        const int* p = (const int*)ei;
        s = p[t];
        d = p[E_EDGES + t];
    }
    g_src[t] = s;
    g_dst[t] = d;
    atomicAdd(&g_cnt[d], 1);
}

// ---------------- chip-wide 3-phase exclusive scan of g_cnt ----------------
// Reads each count exactly once and zeroes it in place (keeps the
// zero-on-entry invariant for the next graph replay; saves a kernel).
__global__ void scan_local_kernel() {
    __shared__ int sh[1024];
    int t = threadIdx.x;
    int i = blockIdx.x * 1024 + t;
    int v = 0;
    if (i < N_NODES) {
        v = g_cnt[i];
        g_cnt[i] = 0;
    }
    sh[t] = v;
    __syncthreads();
    for (int o = 1; o < 1024; o <<= 1) {
        int cur = sh[t];
        int idx = (t >= o) ? (t - o) : 0;   // always valid (no speculative OOB LDS)
        int u = sh[idx];
        u = (t >= o) ? u : 0;
        __syncthreads();
        sh[t] = cur + u;
        __syncthreads();
    }
    if (i < N_NODES) g_off[i] = sh[t] - v;  // exclusive within tile
    if (t == 1023) g_bsum[blockIdx.x] = sh[1023];
}

__global__ void scan_bsum_kernel() {
    __shared__ int sh[64];
    int t = threadIdx.x;   // blockDim.x = 64 >= NB_SCAN
    int v = (t < NB_SCAN) ? g_bsum[t] : 0;
    sh[t] = v;
    __syncthreads();
    for (int o = 1; o < 64; o <<= 1) {
        int cur = sh[t];
        int idx = (t >= o) ? (t - o) : 0;
        int u = sh[idx];
        u = (t >= o) ? u : 0;
        __syncthreads();
        sh[t] = cur + u;
        __syncthreads();
    }
    if (t < NB_SCAN) g_boff[t] = sh[t] - v;  // exclusive
}

__global__ void addoff_kernel() {
    int i = blockIdx.x * blockDim.x + threadIdx.x;
    if (i < N_NODES) {
        int o = g_off[i] + g_boff[i >> 10];
        g_off[i] = o;
        g_cur[i] = o;
    }
    if (i == 0) g_off[N_NODES] = ET;
}

__global__ void scatter_kernel() {
    int t = blockIdx.x * blockDim.x + threadIdx.x;
    if (t >= ET) return;
    int d = g_dst[t];
    int pos = atomicAdd(&g_cur[d], 1);
    g_es[pos] = g_src[t];
}

// ---------------- tf32 tensor-core GEMM, layer 1 (128x128 tile) ------------
__global__ void __launch_bounds__(256) gemm1_kernel(const float* __restrict__ X,
                                                    const float* __restrict__ W) {
    __shared__ float Xs[128][36];   // pad 36: A-frag bank = (4g+tg), conflict-free
    __shared__ float Ws[32][136];   // pad 136: B-frag bank = (8tg+g), conflict-free
    const int tid = threadIdx.x;
    const int warp = tid >> 5, lane = tid & 31;
    const int g = lane >> 2, tg = lane & 3;
    const int base = blockIdx.x * 128;
    const int row0 = warp * 16;

    float d[16][4];
#pragma unroll
    for (int nt = 0; nt < 16; nt++)
#pragma unroll
        for (int j = 0; j < 4; j++) d[nt][j] = 0.0f;

    const int lr = tid >> 1, lh = tid & 1;   // X loader
    const int kw = tid >> 3, seg = tid & 7;  // W loader

    for (int k0 = 0; k0 < 128; k0 += 32) {
        {
            int node = base + lr; if (node >= N_NODES) node = N_NODES - 1;
            const float4* xr = (const float4*)(X + (size_t)node * 128 + k0 + lh * 16);
#pragma unroll
            for (int c = 0; c < 4; c++) {
                float4 v = xr[c];
                int kk = lh * 16 + c * 4;
                Xs[lr][kk + 0] = f2tf32f(v.x); Xs[lr][kk + 1] = f2tf32f(v.y);
                Xs[lr][kk + 2] = f2tf32f(v.z); Xs[lr][kk + 3] = f2tf32f(v.w);
            }
        }
        {
            const float4* wr = (const float4*)(W + (size_t)(k0 + kw) * 128 + seg * 16);
#pragma unroll
            for (int c = 0; c < 4; c++) {
                float4 v = wr[c];
                int cc = seg * 16 + c * 4;
                Ws[kw][cc + 0] = f2tf32f(v.x); Ws[kw][cc + 1] = f2tf32f(v.y);
                Ws[kw][cc + 2] = f2tf32f(v.z); Ws[kw][cc + 3] = f2tf32f(v.w);
            }
        }
        __syncthreads();
#pragma unroll
        for (int ks = 0; ks < 4; ks++) {
            int kk = ks * 8;
            unsigned a0 = __float_as_uint(Xs[row0 + g][kk + tg]);
            unsigned a1 = __float_as_uint(Xs[row0 + g + 8][kk + tg]);
            unsigned a2 = __float_as_uint(Xs[row0 + g][kk + tg + 4]);
            unsigned a3 = __float_as_uint(Xs[row0 + g + 8][kk + tg + 4]);
#pragma unroll
            for (int nt = 0; nt < 16; nt++) {
                unsigned b0 = __float_as_uint(Ws[kk + tg][nt * 8 + g]);
                unsigned b1 = __float_as_uint(Ws[kk + tg + 4][nt * 8 + g]);
                mma_tf32(d[nt], a0, a1, a2, a3, b0, b1);
            }
        }
        __syncthreads();
    }
#pragma unroll
    for (int nt = 0; nt < 16; nt++) {
        int c = nt * 8 + 2 * tg;
        int n1 = base + row0 + g;
        int n2 = n1 + 8;
        if (n1 < N_NODES) {
            *(float2*)&g_h1[(size_t)n1 * 128 + c] = make_float2(d[nt][0], d[nt][1]);
            __nv_bfloat162 p = __floats2bfloat162_rn(d[nt][0], d[nt][1]);
            *(unsigned*)&g_h1b[(size_t)n1 * 128 + c] = *(unsigned*)&p;
        }
        if (n2 < N_NODES) {
            *(float2*)&g_h1[(size_t)n2 * 128 + c] = make_float2(d[nt][2], d[nt][3]);
            __nv_bfloat162 p = __floats2bfloat162_rn(d[nt][2], d[nt][3]);
            *(unsigned*)&g_h1b[(size_t)n2 * 128 + c] = *(unsigned*)&p;
        }
    }
}

// ---------------- tf32 tensor-core GEMM, layer 2 (128x64 tile) -------------
__global__ void __launch_bounds__(256) gemm2_kernel(const float* __restrict__ W) {
    __shared__ float Xs[128][36];
    __shared__ float Ws[32][72];    // pad 72: B-frag bank = (8tg+g), conflict-free
    const int tid = threadIdx.x;
    const int warp = tid >> 5, lane = tid & 31;
    const int g = lane >> 2, tg = lane & 3;
    const int base = blockIdx.x * 128;
    const int row0 = warp * 16;

    float d[8][4];
#pragma unroll
    for (int nt = 0; nt < 8; nt++)
#pragma unroll
        for (int j = 0; j < 4; j++) d[nt][j] = 0.0f;

    const int lr = tid >> 1, lh = tid & 1;   // X loader
    const int kw = tid >> 3, seg = tid & 7;  // W loader

    for (int k0 = 0; k0 < 128; k0 += 32) {
        {
            int node = base + lr; if (node >= N_NODES) node = N_NODES - 1;
            const float4* xr = (const float4*)(g_out1 + (size_t)node * 128 + k0 + lh * 16);
#pragma unroll
            for (int c = 0; c < 4; c++) {
                float4 v = xr[c];
                int kk = lh * 16 + c * 4;
                Xs[lr][kk + 0] = f2tf32f(v.x); Xs[lr][kk + 1] = f2tf32f(v.y);
                Xs[lr][kk + 2] = f2tf32f(v.z); Xs[lr][kk + 3] = f2tf32f(v.w);
            }
        }
        {
            const float4* wr = (const float4*)(W + (size_t)(k0 + kw) * 64 + seg * 8);
#pragma unroll
            for (int c = 0; c < 2; c++) {
                float4 v = wr[c];
                int cc = seg * 8 + c * 4;
                Ws[kw][cc + 0] = f2tf32f(v.x); Ws[kw][cc + 1] = f2tf32f(v.y);
                Ws[kw][cc + 2] = f2tf32f(v.z); Ws[kw][cc + 3] = f2tf32f(v.w);
            }
        }
        __syncthreads();
#pragma unroll
        for (int ks = 0; ks < 4; ks++) {
            int kk = ks * 8;
            unsigned a0 = __float_as_uint(Xs[row0 + g][kk + tg]);
            unsigned a1 = __float_as_uint(Xs[row0 + g + 8][kk + tg]);
            unsigned a2 = __float_as_uint(Xs[row0 + g][kk + tg + 4]);
            unsigned a3 = __float_as_uint(Xs[row0 + g + 8][kk + tg + 4]);
#pragma unroll
            for (int nt = 0; nt < 8; nt++) {
                unsigned b0 = __float_as_uint(Ws[kk + tg][nt * 8 + g]);
                unsigned b1 = __float_as_uint(Ws[kk + tg + 4][nt * 8 + g]);
                mma_tf32(d[nt], a0, a1, a2, a3, b0, b1);
            }
        }
        __syncthreads();
    }
#pragma unroll
    for (int nt = 0; nt < 8; nt++) {
        int c = nt * 8 + 2 * tg;
        int n1 = base + row0 + g;
        int n2 = n1 + 8;
        if (n1 < N_NODES) {
            *(float2*)&g_h2[(size_t)n1 * 64 + c] = make_float2(d[nt][0], d[nt][1]);
            __nv_bfloat162 p = __floats2bfloat162_rn(d[nt][0], d[nt][1]);
            *(unsigned*)&g_h2b[(size_t)n1 * 64 + c] = *(unsigned*)&p;
        }
        if (n2 < N_NODES) {
            *(float2*)&g_h2[(size_t)n2 * 64 + c] = make_float2(d[nt][2], d[nt][3]);
            __nv_bfloat162 p = __floats2bfloat162_rn(d[nt][2], d[nt][3]);
            *(unsigned*)&g_h2b[(size_t)n2 * 64 + c] = *(unsigned*)&p;
        }
    }
}

// ---------------- attention terms ----------------
__global__ void alpha1_kernel(const float* __restrict__ a_s,
                              const float* __restrict__ a_d) {
    int t = blockIdx.x * blockDim.x + threadIdx.x;
    if (t >= N_NODES * HEADS) return;
    int n = t >> 3, h = t & 7;
    const float* row = g_h1 + (size_t)n * HID + h * C1;
    float s = 0.0f, d = 0.0f;
#pragma unroll
    for (int c = 0; c < C1; c++) {
        float v = row[c];
        s += v * a_s[h * C1 + c];
        d += v * a_d[h * C1 + c];
    }
    g_as1[t] = s;
    g_ad1[t] = d;
}

__global__ void alpha2_kernel(const float* __restrict__ a_s,
                              const float* __restrict__ a_d) {
    int n = blockIdx.x * blockDim.x + threadIdx.x;
    if (n >= N_NODES) return;
    const float* row = g_h2 + (size_t)n * OUT_DIM;
    float s = 0.0f, d = 0.0f;
#pragma unroll
    for (int c = 0; c < OUT_DIM; c++) {
        float v = row[c];
        s += v * a_s[c];
        d += v * a_d[c];
    }
    g_as2[n] = s;
    g_ad2[n] = d;
}

// ---------------- CSR aggregation, layer 1 (R11 form: bf16 8B gathers) -----
__global__ void __launch_bounds__(256) agg1_csr_kernel(const float* __restrict__ b1) {
    const unsigned FULL = 0xffffffffu;
    int n = (blockIdx.x * blockDim.x + threadIdx.x) >> 5;
    int lane = threadIdx.x & 31;
    if (n >= N_NODES) return;
    int beg = g_off[n], end = g_off[n + 1];
    int h = lane & 7;          // head for score phase
    int eslot = lane >> 3;     // 0..3: which edge of the group
    float ad = g_ad1[n * HEADS + h];
    float4 acc = make_float4(0.f, 0.f, 0.f, 0.f);
    float den = 0.0f;

    int cnt = end - beg;
    int nfull = cnt & ~3;
    int pfull = beg + nfull;

    for (int p = beg; p < pfull; p += 4) {
        int src = g_es[p + eslot];
        float sc = g_as1[src * HEADS + h] + ad;
        sc = (sc >= 0.0f) ? sc : NEG_SLOPE * sc;
        float e = expf(sc);
        den += e;
#pragma unroll
        for (int j = 0; j < 4; j++) {
            int srcj = __shfl_sync(FULL, src, j * 8);
            float ej = __shfl_sync(FULL, e, j * 8 + (lane >> 2));
            uint2 raw = ((const uint2*)(g_h1b + (size_t)srcj * 128))[lane];
            float2 f0 = __bfloat1622float2(*(__nv_bfloat162*)&raw.x);
            float2 f1 = __bfloat1622float2(*(__nv_bfloat162*)&raw.y);
            acc.x += f0.x * ej; acc.y += f0.y * ej;
            acc.z += f1.x * ej; acc.w += f1.y * ej;
        }
    }
    int rem = cnt - nfull;     // 0..3, uniform across warp
    if (rem) {
        int eidx = pfull + eslot;
        int src = g_es[(eidx < end) ? eidx : beg];
        float sc = g_as1[src * HEADS + h] + ad;
        sc = (sc >= 0.0f) ? sc : NEG_SLOPE * sc;
        float e = (eslot < rem) ? expf(sc) : 0.0f;
        den += e;
        for (int j = 0; j < rem; j++) {
            int srcj = __shfl_sync(FULL, src, j * 8);
            float ej = __shfl_sync(FULL, e, j * 8 + (lane >> 2));
            uint2 raw = ((const uint2*)(g_h1b + (size_t)srcj * 128))[lane];
            float2 f0 = __bfloat1622float2(*(__nv_bfloat162*)&raw.x);
            float2 f1 = __bfloat1622float2(*(__nv_bfloat162*)&raw.y);
            acc.x += f0.x * ej; acc.y += f0.y * ej;
            acc.z += f1.x * ej; acc.w += f1.y * ej;
        }
    }
    den += __shfl_xor_sync(FULL, den, 8);
    den += __shfl_xor_sync(FULL, den, 16);
    float dh = __shfl_sync(FULL, den, lane >> 2);
    float inv = 1.0f / dh;
    const float4 bb = ((const float4*)b1)[lane];
    float4 r;
    r.x = acc.x * inv + bb.x; r.y = acc.y * inv + bb.y;
    r.z = acc.z * inv + bb.z; r.w = acc.w * inv + bb.w;
    r.x = (r.x > 0.f) ? r.x : expm1f(r.x);
    r.y = (r.y > 0.f) ? r.y : expm1f(r.y);
    r.z = (r.z > 0.f) ? r.z : expm1f(r.z);
    r.w = (r.w > 0.f) ? r.w : expm1f(r.w);
    ((float4*)(g_out1 + (size_t)n * 128))[lane] = r;
}

// ---------------- CSR aggregation + log_softmax, layer 2 (R11 form) --------
__global__ void __launch_bounds__(256) agg2_csr_kernel(const float* __restrict__ b2,
                                                       float* __restrict__ out) {
    int hw = (blockIdx.x * blockDim.x + threadIdx.x) >> 4;  // node id
    int lane = threadIdx.x & 31;
    int l = lane & 15;
    const unsigned mask = 0xffffu << (lane & 16);  // own half-warp only (R5 lesson)
    if (hw >= N_NODES) return;
    int n = hw;
    int beg = g_off[n], end = g_off[n + 1];
    float ad = g_ad2[n];
    float4 acc = make_float4(0.f, 0.f, 0.f, 0.f);
    float den = 0.0f;

    int cnt = end - beg;
    int nfull = cnt & ~15;
    int pfull = beg + nfull;

    for (int p = beg; p < pfull; p += 16) {
        int src = g_es[p + l];
        float sc = g_as2[src] + ad;
        sc = (sc >= 0.0f) ? sc : NEG_SLOPE * sc;
        float e = expf(sc);
        den += e;
#pragma unroll
        for (int j = 0; j < 16; j++) {
            int srcj = __shfl_sync(mask, src, j, 16);
            float ej = __shfl_sync(mask, e, j, 16);
            uint2 raw = ((const uint2*)(g_h2b + (size_t)srcj * 64))[l];
            float2 f0 = __bfloat1622float2(*(__nv_bfloat162*)&raw.x);
            float2 f1 = __bfloat1622float2(*(__nv_bfloat162*)&raw.y);
            acc.x += f0.x * ej; acc.y += f0.y * ej;
            acc.z += f1.x * ej; acc.w += f1.y * ej;
        }
    }
    int rem = cnt - nfull;   // 0..15, uniform across half-warp
    if (rem) {
        int eidx = pfull + l;
        int src = g_es[(eidx < end) ? eidx : beg];
        float sc = g_as2[src] + ad;
        sc = (sc >= 0.0f) ? sc : NEG_SLOPE * sc;
        float e = (l < rem) ? expf(sc) : 0.0f;
        den += e;
        for (int j = 0; j < rem; j++) {
            int srcj = __shfl_sync(mask, src, j, 16);
            float ej = __shfl_sync(mask, e, j, 16);
            uint2 raw = ((const uint2*)(g_h2b + (size_t)srcj * 64))[l];
            float2 f0 = __bfloat1622float2(*(__nv_bfloat162*)&raw.x);
            float2 f1 = __bfloat1622float2(*(__nv_bfloat162*)&raw.y);
            acc.x += f0.x * ej; acc.y += f0.y * ej;
            acc.z += f1.x * ej; acc.w += f1.y * ej;
        }
    }
#pragma unroll
    for (int o = 8; o; o >>= 1) den += __shfl_xor_sync(mask, den, o, 16);
    float inv = 1.0f / den;
    const float4 bb = ((const float4*)b2)[l];
    float v[4];
    v[0] = acc.x * inv + bb.x; v[1] = acc.y * inv + bb.y;
    v[2] = acc.z * inv + bb.z; v[3] = acc.w * inv + bb.w;
    float m = fmaxf(fmaxf(v[0], v[1]), fmaxf(v[2], v[3]));
#pragma unroll
    for (int o = 8; o; o >>= 1) m = fmaxf(m, __shfl_xor_sync(mask, m, o, 16));
    float s = expf(v[0] - m) + expf(v[1] - m) + expf(v[2] - m) + expf(v[3] - m);
#pragma unroll
    for (int o = 8; o; o >>= 1) s += __shfl_xor_sync(mask, s, o, 16);
    float lse = m + logf(s);
    ((float4*)(out + (size_t)n * 64))[l] =
        make_float4(v[0] - lse, v[1] - lse, v[2] - lse, v[3] - lse);
}

// ---------------- launch ----------------
extern "C" void kernel_launch(void* const* d_in, const int* in_sizes, int n_in,
                              void* d_out, int out_size) {
    const float* x   = (const float*)d_in[0];
    const void*  ei  = d_in[1];
    const float* W1  = (const float*)d_in[2];
    const float* as1 = (const float*)d_in[3];
    const float* ad1 = (const float*)d_in[4];
    const float* b1  = (const float*)d_in[5];
    const float* W2  = (const float*)d_in[6];
    const float* as2 = (const float*)d_in[7];
    const float* ad2 = (const float*)d_in[8];
    const float* b2  = (const float*)d_in[9];
    float* out = (float*)d_out;

    // ---- fork: CSR build on side stream, concurrent with gemm1/alpha1 ----
    cudaStream_t sb = g_aux.ok ? g_aux.s2 : 0;
    if (g_aux.ok) {
        cudaEventRecord(g_aux.fork, 0);
        cudaStreamWaitEvent(g_aux.s2, g_aux.fork, 0);
    }
    detect_kernel<<<1, 1024, 0, sb>>>((const unsigned long long*)ei);
    convert_hist_kernel<<<(ET + 255) / 256, 256, 0, sb>>>(ei);
    scan_local_kernel<<<NB_SCAN, 1024, 0, sb>>>();
    scan_bsum_kernel<<<1, 64, 0, sb>>>();
    addoff_kernel<<<(N_NODES + 255) / 256, 256, 0, sb>>>();
    scatter_kernel<<<(ET + 255) / 256, 256, 0, sb>>>();
    if (g_aux.ok) cudaEventRecord(g_aux.join, g_aux.s2);

    // ---- main stream: layer-1 dense work (independent of CSR) ----
    gemm1_kernel<<<(N_NODES + 127) / 128, 256>>>(x, W1);
    alpha1_kernel<<<(N_NODES * HEADS + 255) / 256, 256>>>(as1, ad1);

    // ---- join: aggregation needs the CSR ----
    if (g_aux.ok) cudaStreamWaitEvent(0, g_aux.join, 0);
    agg1_csr_kernel<<<(N_NODES * 32 + 255) / 256, 256>>>(b1);

    // ---- layer 2 ----
    gemm2_kernel<<<(N_NODES + 127) / 128, 256>>>(W2);
    alpha2_kernel<<<(N_NODES + 255) / 256, 256>>>(as2, ad2);
    agg2_csr_kernel<<<(N_NODES * 16 + 255) / 256, 256>>>(b2, out);
}

// round 15
// speedup vs baseline: 1.5580x; 1.0737x over previous
#include <cuda_runtime.h>
#include <cuda_bf16.h>
#include <math.h>

#define N_NODES 50000
#define E_EDGES 800000
#define ET (E_EDGES + N_NODES)   /* 850000 edges incl. self loops */
#define HID 128
#define HEADS 8
#define C1 16
#define OUT_DIM 64
#define NEG_SLOPE 0.2f
#define NB_SCAN ((N_NODES + 1023) / 1024)   /* 49 scan tiles */

// ---------------- scratch (device globals; no allocation) ----------------
__device__ __align__(16) float g_h1[N_NODES * HID];    // layer1 projection (fp32, for scores)
__device__ __align__(16) __nv_bfloat16 g_h1b[N_NODES * HID];   // bf16 copy (gather payload)
__device__ __align__(16) float g_out1[N_NODES * HID];  // layer1 output (post-ELU)
__device__ __align__(16) float g_h2[N_NODES * OUT_DIM];
__device__ __align__(16) __nv_bfloat16 g_h2b[N_NODES * OUT_DIM];
__device__ float g_as1[N_NODES * HEADS];
__device__ float g_ad1[N_NODES * HEADS];
__device__ float g_as2[N_NODES];
__device__ float g_ad2[N_NODES];
__device__ int   g_src[ET];
__device__ int   g_dst[ET];
__device__ int   g_es[ET];          // src ids sorted by dst (CSR values)
__device__ int   g_cnt[N_NODES];    // zero at call entry (scan_local re-zeroes)
__device__ int   g_off[N_NODES + 1];
__device__ int   g_cur[N_NODES];
__device__ int   g_bsum[NB_SCAN];
__device__ int   g_boff[NB_SCAN];
__device__ int   g_is64;

// ---------------- side stream for CSR-build / GEMM overlap ----------------
namespace {
struct AuxStreams {
    cudaStream_t s2 = 0;
    cudaEvent_t  fork = 0, join = 0;
    bool ok = false;
    AuxStreams() {
        if (cudaStreamCreateWithFlags(&s2, cudaStreamNonBlocking) == cudaSuccess &&
            cudaEventCreateWithFlags(&fork, cudaEventDisableTiming) == cudaSuccess &&
            cudaEventCreateWithFlags(&join, cudaEventDisableTiming) == cudaSuccess) {
            ok = true;
        } else {
            s2 = 0;
            ok = false;
        }
    }
};
AuxStreams g_aux;
}

// ---------------- tf32 helpers ----------------
__device__ __forceinline__ float f2tf32f(float f) {
    unsigned r;
    asm("cvt.rna.tf32.f32 %0, %1;" : "=r"(r) : "f"(f));
    return __uint_as_float(r);
}
__device__ __forceinline__ void mma_tf32(float* d, unsigned a0, unsigned a1,
                                         unsigned a2, unsigned a3,
                                         unsigned b0, unsigned b1) {
    asm volatile(
        "mma.sync.aligned.m16n8k8.row.col.f32.tf32.tf32.f32 "
        "{%0,%1,%2,%3}, {%4,%5,%6,%7}, {%8,%9}, {%0,%1,%2,%3};"
        : "+f"(d[0]), "+f"(d[1]), "+f"(d[2]), "+f"(d[3])
        : "r"(a0), "r"(a1), "r"(a2), "r"(a3), "r"(b0), "r"(b1));
}

// ---------------- edge dtype detection ----------------
__global__ void detect_kernel(const unsigned long long* __restrict__ e64) {
    __shared__ int bad;
    if (threadIdx.x == 0) bad = 0;
    __syncthreads();
    unsigned long long v = e64[threadIdx.x];  // blockDim.x = 1024
    if (v >= (unsigned long long)N_NODES) atomicOr(&bad, 1);
    __syncthreads();
    if (threadIdx.x == 0) g_is64 = bad ? 0 : 1;
}

// decode edges (+self loops), stage src/dst, histogram destinations.
__global__ void convert_hist_kernel(const void* __restrict__ ei) {
    int t = blockIdx.x * blockDim.x + threadIdx.x;
    if (t >= ET) return;
    int s, d;
    if (t >= E_EDGES) {
        s = d = t - E_EDGES;
    } else if (g_is64) {
        const long long* p = (const long long*)ei;
        s = (int)p[t];
        d = (int)p[E_EDGES + t];
    } else {
        const int* p = (const int*)ei;
        s = p[t];
        d = p[E_EDGES + t];
    }
    g_src[t] = s;
    g_dst[t] = d;
    atomicAdd(&g_cnt[d], 1);
}

// ---------------- chip-wide 3-phase exclusive scan of g_cnt ----------------
__global__ void scan_local_kernel() {
    __shared__ int sh[1024];
    int t = threadIdx.x;
    int i = blockIdx.x * 1024 + t;
    int v = 0;
    if (i < N_NODES) {
        v = g_cnt[i];
        g_cnt[i] = 0;    // keep zero-on-entry invariant for next replay
    }
    sh[t] = v;
    __syncthreads();
    for (int o = 1; o < 1024; o <<= 1) {
        int cur = sh[t];
        int idx = (t >= o) ? (t - o) : 0;   // always valid (no speculative OOB LDS)
        int u = sh[idx];
        u = (t >= o) ? u : 0;
        __syncthreads();
        sh[t] = cur + u;
        __syncthreads();
    }
    if (i < N_NODES) g_off[i] = sh[t] - v;  // exclusive within tile
    if (t == 1023) g_bsum[blockIdx.x] = sh[1023];
}

__global__ void scan_bsum_kernel() {
    __shared__ int sh[64];
    int t = threadIdx.x;   // blockDim.x = 64 >= NB_SCAN
    int v = (t < NB_SCAN) ? g_bsum[t] : 0;
    sh[t] = v;
    __syncthreads();
    for (int o = 1; o < 64; o <<= 1) {
        int cur = sh[t];
        int idx = (t >= o) ? (t - o) : 0;
        int u = sh[idx];
        u = (t >= o) ? u : 0;
        __syncthreads();
        sh[t] = cur + u;
        __syncthreads();
    }
    if (t < NB_SCAN) g_boff[t] = sh[t] - v;  // exclusive
}

__global__ void addoff_kernel() {
    int i = blockIdx.x * blockDim.x + threadIdx.x;
    if (i < N_NODES) {
        int o = g_off[i] + g_boff[i >> 10];
        g_off[i] = o;
        g_cur[i] = o;
    }
    if (i == 0) g_off[N_NODES] = ET;
}

__global__ void scatter_kernel() {
    int t = blockIdx.x * blockDim.x + threadIdx.x;
    if (t >= ET) return;
    int d = g_dst[t];
    int pos = atomicAdd(&g_cur[d], 1);
    g_es[pos] = g_src[t];
}

// ---------------- tf32 GEMM layer 1 + fused alpha epilogue -----------------
// alpha_s/alpha_d per (row, head) computed from register-resident results:
// head hh owns cols 16hh..16hh+15 = nt in {2hh, 2hh+1}; a_s1/a_d1 flat index
// equals column index. Partial dot per lane, reduced over the 4 tg-lanes.
__global__ void __launch_bounds__(256) gemm1_kernel(const float* __restrict__ X,
                                                    const float* __restrict__ W,
                                                    const float* __restrict__ a_s,
                                                    const float* __restrict__ a_d) {
    __shared__ float Xs[128][36];   // pad 36: A-frag bank = (4g+tg), conflict-free
    __shared__ float Ws[32][136];   // pad 136: B-frag bank = (8tg+g), conflict-free
    const int tid = threadIdx.x;
    const int warp = tid >> 5, lane = tid & 31;
    const int g = lane >> 2, tg = lane & 3;
    const int base = blockIdx.x * 128;
    const int row0 = warp * 16;

    float d[16][4];
#pragma unroll
    for (int nt = 0; nt < 16; nt++)
#pragma unroll
        for (int j = 0; j < 4; j++) d[nt][j] = 0.0f;

    const int lr = tid >> 1, lh = tid & 1;   // X loader
    const int kw = tid >> 3, seg = tid & 7;  // W loader

    for (int k0 = 0; k0 < 128; k0 += 32) {
        {
            int node = base + lr; if (node >= N_NODES) node = N_NODES - 1;
            const float4* xr = (const float4*)(X + (size_t)node * 128 + k0 + lh * 16);
#pragma unroll
            for (int c = 0; c < 4; c++) {
                float4 v = xr[c];
                int kk = lh * 16 + c * 4;
                Xs[lr][kk + 0] = f2tf32f(v.x); Xs[lr][kk + 1] = f2tf32f(v.y);
                Xs[lr][kk + 2] = f2tf32f(v.z); Xs[lr][kk + 3] = f2tf32f(v.w);
            }
        }
        {
            const float4* wr = (const float4*)(W + (size_t)(k0 + kw) * 128 + seg * 16);
#pragma unroll
            for (int c = 0; c < 4; c++) {
                float4 v = wr[c];
                int cc = seg * 16 + c * 4;
                Ws[kw][cc + 0] = f2tf32f(v.x); Ws[kw][cc + 1] = f2tf32f(v.y);
                Ws[kw][cc + 2] = f2tf32f(v.z); Ws[kw][cc + 3] = f2tf32f(v.w);
            }
        }
        __syncthreads();
#pragma unroll
        for (int ks = 0; ks < 4; ks++) {
            int kk = ks * 8;
            unsigned a0 = __float_as_uint(Xs[row0 + g][kk + tg]);
            unsigned a1 = __float_as_uint(Xs[row0 + g + 8][kk + tg]);
            unsigned a2 = __float_as_uint(Xs[row0 + g][kk + tg + 4]);
            unsigned a3 = __float_as_uint(Xs[row0 + g + 8][kk + tg + 4]);
#pragma unroll
            for (int nt = 0; nt < 16; nt++) {
                unsigned b0 = __float_as_uint(Ws[kk + tg][nt * 8 + g]);
                unsigned b1 = __float_as_uint(Ws[kk + tg + 4][nt * 8 + g]);
                mma_tf32(d[nt], a0, a1, a2, a3, b0, b1);
            }
        }
        __syncthreads();
    }

    const unsigned FULL = 0xffffffffu;
    int n1 = base + row0 + g;
    int n2 = n1 + 8;

    // fused alpha: per-lane partial dots with a_s/a_d, reduced over tg lanes
    float ps1[8], pd1[8], ps2[8], pd2[8];
#pragma unroll
    for (int hh = 0; hh < 8; hh++) { ps1[hh] = pd1[hh] = ps2[hh] = pd2[hh] = 0.0f; }
#pragma unroll
    for (int nt = 0; nt < 16; nt++) {
        int c = nt * 8 + 2 * tg;
        float sa0 = __ldg(&a_s[c]), sa1 = __ldg(&a_s[c + 1]);
        float da0 = __ldg(&a_d[c]), da1 = __ldg(&a_d[c + 1]);
        int hh = nt >> 1;
        ps1[hh] += d[nt][0] * sa0 + d[nt][1] * sa1;
        pd1[hh] += d[nt][0] * da0 + d[nt][1] * da1;
        ps2[hh] += d[nt][2] * sa0 + d[nt][3] * sa1;
        pd2[hh] += d[nt][2] * da0 + d[nt][3] * da1;
    }
#pragma unroll
    for (int hh = 0; hh < 8; hh++) {
        ps1[hh] += __shfl_xor_sync(FULL, ps1[hh], 1);
        ps1[hh] += __shfl_xor_sync(FULL, ps1[hh], 2);
        pd1[hh] += __shfl_xor_sync(FULL, pd1[hh], 1);
        pd1[hh] += __shfl_xor_sync(FULL, pd1[hh], 2);
        ps2[hh] += __shfl_xor_sync(FULL, ps2[hh], 1);
        ps2[hh] += __shfl_xor_sync(FULL, ps2[hh], 2);
        pd2[hh] += __shfl_xor_sync(FULL, pd2[hh], 1);
        pd2[hh] += __shfl_xor_sync(FULL, pd2[hh], 2);
    }
    if (tg < 2) {
        // tg==0 writes as, tg==1 writes ad (spread the stores)
        if (n1 < N_NODES) {
#pragma unroll
            for (int hh = 0; hh < 8; hh++) {
                if (tg == 0) g_as1[n1 * 8 + hh] = ps1[hh];
                else         g_ad1[n1 * 8 + hh] = pd1[hh];
            }
        }
        if (n2 < N_NODES) {
#pragma unroll
            for (int hh = 0; hh < 8; hh++) {
                if (tg == 0) g_as1[n2 * 8 + hh] = ps2[hh];
                else         g_ad1[n2 * 8 + hh] = pd2[hh];
            }
        }
    }

    // main result stores (fp32 + bf16 copy)
#pragma unroll
    for (int nt = 0; nt < 16; nt++) {
        int c = nt * 8 + 2 * tg;
        if (n1 < N_NODES) {
            *(float2*)&g_h1[(size_t)n1 * 128 + c] = make_float2(d[nt][0], d[nt][1]);
            __nv_bfloat162 p = __floats2bfloat162_rn(d[nt][0], d[nt][1]);
            *(unsigned*)&g_h1b[(size_t)n1 * 128 + c] = *(unsigned*)&p;
        }
        if (n2 < N_NODES) {
            *(float2*)&g_h1[(size_t)n2 * 128 + c] = make_float2(d[nt][2], d[nt][3]);
            __nv_bfloat162 p = __floats2bfloat162_rn(d[nt][2], d[nt][3]);
            *(unsigned*)&g_h1b[(size_t)n2 * 128 + c] = *(unsigned*)&p;
        }
    }
}

// ---------------- tf32 GEMM layer 2 + fused alpha epilogue -----------------
__global__ void __launch_bounds__(256) gemm2_kernel(const float* __restrict__ W,
                                                    const float* __restrict__ a_s,
                                                    const float* __restrict__ a_d) {
    __shared__ float Xs[128][36];
    __shared__ float Ws[32][72];    // pad 72: B-frag bank = (8tg+g), conflict-free
    const int tid = threadIdx.x;
    const int warp = tid >> 5, lane = tid & 31;
    const int g = lane >> 2, tg = lane & 3;
    const int base = blockIdx.x * 128;
    const int row0 = warp * 16;

    float d[8][4];
#pragma unroll
    for (int nt = 0; nt < 8; nt++)
#pragma unroll
        for (int j = 0; j < 4; j++) d[nt][j] = 0.0f;

    const int lr = tid >> 1, lh = tid & 1;   // X loader
    const int kw = tid >> 3, seg = tid & 7;  // W loader

    for (int k0 = 0; k0 < 128; k0 += 32) {
        {
            int node = base + lr; if (node >= N_NODES) node = N_NODES - 1;
            const float4* xr = (const float4*)(g_out1 + (size_t)node * 128 + k0 + lh * 16);
#pragma unroll
            for (int c = 0; c < 4; c++) {
                float4 v = xr[c];
                int kk = lh * 16 + c * 4;
                Xs[lr][kk + 0] = f2tf32f(v.x); Xs[lr][kk + 1] = f2tf32f(v.y);
                Xs[lr][kk + 2] = f2tf32f(v.z); Xs[lr][kk + 3] = f2tf32f(v.w);
            }
        }
        {
            const float4* wr = (const float4*)(W + (size_t)(k0 + kw) * 64 + seg * 8);
#pragma unroll
            for (int c = 0; c < 2; c++) {
                float4 v = wr[c];
                int cc = seg * 8 + c * 4;
                Ws[kw][cc + 0] = f2tf32f(v.x); Ws[kw][cc + 1] = f2tf32f(v.y);
                Ws[kw][cc + 2] = f2tf32f(v.z); Ws[kw][cc + 3] = f2tf32f(v.w);
            }
        }
        __syncthreads();
#pragma unroll
        for (int ks = 0; ks < 4; ks++) {
            int kk = ks * 8;
            unsigned a0 = __float_as_uint(Xs[row0 + g][kk + tg]);
            unsigned a1 = __float_as_uint(Xs[row0 + g + 8][kk + tg]);
            unsigned a2 = __float_as_uint(Xs[row0 + g][kk + tg + 4]);
            unsigned a3 = __float_as_uint(Xs[row0 + g + 8][kk + tg + 4]);
#pragma unroll
            for (int nt = 0; nt < 8; nt++) {
                unsigned b0 = __float_as_uint(Ws[kk + tg][nt * 8 + g]);
                unsigned b1 = __float_as_uint(Ws[kk + tg + 4][nt * 8 + g]);
                mma_tf32(d[nt], a0, a1, a2, a3, b0, b1);
            }
        }
        __syncthreads();
    }

    const unsigned FULL = 0xffffffffu;
    int n1 = base + row0 + g;
    int n2 = n1 + 8;

    // fused alpha: single scalar per row (one "head" over 64 cols)
    float ps1 = 0.f, pd1 = 0.f, ps2 = 0.f, pd2 = 0.f;
#pragma unroll
    for (int nt = 0; nt < 8; nt++) {
        int c = nt * 8 + 2 * tg;
        float sa0 = __ldg(&a_s[c]), sa1 = __ldg(&a_s[c + 1]);
        float da0 = __ldg(&a_d[c]), da1 = __ldg(&a_d[c + 1]);
        ps1 += d[nt][0] * sa0 + d[nt][1] * sa1;
        pd1 += d[nt][0] * da0 + d[nt][1] * da1;
        ps2 += d[nt][2] * sa0 + d[nt][3] * sa1;
        pd2 += d[nt][2] * da0 + d[nt][3] * da1;
    }
    ps1 += __shfl_xor_sync(FULL, ps1, 1); ps1 += __shfl_xor_sync(FULL, ps1, 2);
    pd1 += __shfl_xor_sync(FULL, pd1, 1); pd1 += __shfl_xor_sync(FULL, pd1, 2);
    ps2 += __shfl_xor_sync(FULL, ps2, 1); ps2 += __shfl_xor_sync(FULL, ps2, 2);
    pd2 += __shfl_xor_sync(FULL, pd2, 1); pd2 += __shfl_xor_sync(FULL, pd2, 2);
    if (tg == 0) {
        if (n1 < N_NODES) { g_as2[n1] = ps1; g_ad2[n1] = pd1; }
        if (n2 < N_NODES) { g_as2[n2] = ps2; g_ad2[n2] = pd2; }
    }

#pragma unroll
    for (int nt = 0; nt < 8; nt++) {
        int c = nt * 8 + 2 * tg;
        if (n1 < N_NODES) {
            *(float2*)&g_h2[(size_t)n1 * 64 + c] = make_float2(d[nt][0], d[nt][1]);
            __nv_bfloat162 p = __floats2bfloat162_rn(d[nt][0], d[nt][1]);
            *(unsigned*)&g_h2b[(size_t)n1 * 64 + c] = *(unsigned*)&p;
        }
        if (n2 < N_NODES) {
            *(float2*)&g_h2[(size_t)n2 * 64 + c] = make_float2(d[nt][2], d[nt][3]);
            __nv_bfloat162 p = __floats2bfloat162_rn(d[nt][2], d[nt][3]);
            *(unsigned*)&g_h2b[(size_t)n2 * 64 + c] = *(unsigned*)&p;
        }
    }
}

// ---------------- CSR aggregation, layer 1 (R11 form: bf16 8B gathers) -----
__global__ void __launch_bounds__(256) agg1_csr_kernel(const float* __restrict__ b1) {
    const unsigned FULL = 0xffffffffu;
    int n = (blockIdx.x * blockDim.x + threadIdx.x) >> 5;
    int lane = threadIdx.x & 31;
    if (n >= N_NODES) return;
    int beg = g_off[n], end = g_off[n + 1];
    int h = lane & 7;          // head for score phase
    int eslot = lane >> 3;     // 0..3: which edge of the group
    float ad = g_ad1[n * HEADS + h];
    float4 acc = make_float4(0.f, 0.f, 0.f, 0.f);
    float den = 0.0f;

    int cnt = end - beg;
    int nfull = cnt & ~3;
    int pfull = beg + nfull;

    for (int p = beg; p < pfull; p += 4) {
        int src = g_es[p + eslot];
        float sc = g_as1[src * HEADS + h] + ad;
        sc = (sc >= 0.0f) ? sc : NEG_SLOPE * sc;
        float e = expf(sc);
        den += e;
#pragma unroll
        for (int j = 0; j < 4; j++) {
            int srcj = __shfl_sync(FULL, src, j * 8);
            float ej = __shfl_sync(FULL, e, j * 8 + (lane >> 2));
            uint2 raw = ((const uint2*)(g_h1b + (size_t)srcj * 128))[lane];
            float2 f0 = __bfloat1622float2(*(__nv_bfloat162*)&raw.x);
            float2 f1 = __bfloat1622float2(*(__nv_bfloat162*)&raw.y);
            acc.x += f0.x * ej; acc.y += f0.y * ej;
            acc.z += f1.x * ej; acc.w += f1.y * ej;
        }
    }
    int rem = cnt - nfull;     // 0..3, uniform across warp
    if (rem) {
        int eidx = pfull + eslot;
        int src = g_es[(eidx < end) ? eidx : beg];
        float sc = g_as1[src * HEADS + h] + ad;
        sc = (sc >= 0.0f) ? sc : NEG_SLOPE * sc;
        float e = (eslot < rem) ? expf(sc) : 0.0f;
        den += e;
        for (int j = 0; j < rem; j++) {
            int srcj = __shfl_sync(FULL, src, j * 8);
            float ej = __shfl_sync(FULL, e, j * 8 + (lane >> 2));
            uint2 raw = ((const uint2*)(g_h1b + (size_t)srcj * 128))[lane];
            float2 f0 = __bfloat1622float2(*(__nv_bfloat162*)&raw.x);
            float2 f1 = __bfloat1622float2(*(__nv_bfloat162*)&raw.y);
            acc.x += f0.x * ej; acc.y += f0.y * ej;
            acc.z += f1.x * ej; acc.w += f1.y * ej;
        }
    }
    den += __shfl_xor_sync(FULL, den, 8);
    den += __shfl_xor_sync(FULL, den, 16);
    float dh = __shfl_sync(FULL, den, lane >> 2);
    float inv = 1.0f / dh;
    const float4 bb = ((const float4*)b1)[lane];
    float4 r;
    r.x = acc.x * inv + bb.x; r.y = acc.y * inv + bb.y;
    r.z = acc.z * inv + bb.z; r.w = acc.w * inv + bb.w;
    r.x = (r.x > 0.f) ? r.x : expm1f(r.x);
    r.y = (r.y > 0.f) ? r.y : expm1f(r.y);
    r.z = (r.z > 0.f) ? r.z : expm1f(r.z);
    r.w = (r.w > 0.f) ? r.w : expm1f(r.w);
    ((float4*)(g_out1 + (size_t)n * 128))[lane] = r;
}

// ---------------- CSR aggregation + log_softmax, layer 2 (R11 form) --------
__global__ void __launch_bounds__(256) agg2_csr_kernel(const float* __restrict__ b2,
                                                       float* __restrict__ out) {
    int hw = (blockIdx.x * blockDim.x + threadIdx.x) >> 4;  // node id
    int lane = threadIdx.x & 31;
    int l = lane & 15;
    const unsigned mask = 0xffffu << (lane & 16);  // own half-warp only (R5 lesson)
    if (hw >= N_NODES) return;
    int n = hw;
    int beg = g_off[n], end = g_off[n + 1];
    float ad = g_ad2[n];
    float4 acc = make_float4(0.f, 0.f, 0.f, 0.f);
    float den = 0.0f;

    int cnt = end - beg;
    int nfull = cnt & ~15;
    int pfull = beg + nfull;

    for (int p = beg; p < pfull; p += 16) {
        int src = g_es[p + l];
        float sc = g_as2[src] + ad;
        sc = (sc >= 0.0f) ? sc : NEG_SLOPE * sc;
        float e = expf(sc);
        den += e;
#pragma unroll
        for (int j = 0; j < 16; j++) {
            int srcj = __shfl_sync(mask, src, j, 16);
            float ej = __shfl_sync(mask, e, j, 16);
            uint2 raw = ((const uint2*)(g_h2b + (size_t)srcj * 64))[l];
            float2 f0 = __bfloat1622float2(*(__nv_bfloat162*)&raw.x);
            float2 f1 = __bfloat1622float2(*(__nv_bfloat162*)&raw.y);
            acc.x += f0.x * ej; acc.y += f0.y * ej;
            acc.z += f1.x * ej; acc.w += f1.y * ej;
        }
    }
    int rem = cnt - nfull;   // 0..15, uniform across half-warp
    if (rem) {
        int eidx = pfull + l;
        int src = g_es[(eidx < end) ? eidx : beg];
        float sc = g_as2[src] + ad;
        sc = (sc >= 0.0f) ? sc : NEG_SLOPE * sc;
        float e = (l < rem) ? expf(sc) : 0.0f;
        den += e;
        for (int j = 0; j < rem; j++) {
            int srcj = __shfl_sync(mask, src, j, 16);
            float ej = __shfl_sync(mask, e, j, 16);
            uint2 raw = ((const uint2*)(g_h2b + (size_t)srcj * 64))[l];
            float2 f0 = __bfloat1622float2(*(__nv_bfloat162*)&raw.x);
            float2 f1 = __bfloat1622float2(*(__nv_bfloat162*)&raw.y);
            acc.x += f0.x * ej; acc.y += f0.y * ej;
            acc.z += f1.x * ej; acc.w += f1.y * ej;
        }
    }
#pragma unroll
    for (int o = 8; o; o >>= 1) den += __shfl_xor_sync(mask, den, o, 16);
    float inv = 1.0f / den;
    const float4 bb = ((const float4*)b2)[l];
    float v[4];
    v[0] = acc.x * inv + bb.x; v[1] = acc.y * inv + bb.y;
    v[2] = acc.z * inv + bb.z; v[3] = acc.w * inv + bb.w;
    float m = fmaxf(fmaxf(v[0], v[1]), fmaxf(v[2], v[3]));
#pragma unroll
    for (int o = 8; o; o >>= 1) m = fmaxf(m, __shfl_xor_sync(mask, m, o, 16));
    float s = expf(v[0] - m) + expf(v[1] - m) + expf(v[2] - m) + expf(v[3] - m);
#pragma unroll
    for (int o = 8; o; o >>= 1) s += __shfl_xor_sync(mask, s, o, 16);
    float lse = m + logf(s);
    ((float4*)(out + (size_t)n * 64))[l] =
        make_float4(v[0] - lse, v[1] - lse, v[2] - lse, v[3] - lse);
}

// ---------------- launch ----------------
extern "C" void kernel_launch(void* const* d_in, const int* in_sizes, int n_in,
                              void* d_out, int out_size) {
    const float* x   = (const float*)d_in[0];
    const void*  ei  = d_in[1];
    const float* W1  = (const float*)d_in[2];
    const float* as1 = (const float*)d_in[3];
    const float* ad1 = (const float*)d_in[4];
    const float* b1  = (const float*)d_in[5];
    const float* W2  = (const float*)d_in[6];
    const float* as2 = (const float*)d_in[7];
    const float* ad2 = (const float*)d_in[8];
    const float* b2  = (const float*)d_in[9];
    float* out = (float*)d_out;

    // ---- fork: CSR build on side stream, concurrent with gemm1 ----
    cudaStream_t sb = g_aux.ok ? g_aux.s2 : 0;
    if (g_aux.ok) {
        cudaEventRecord(g_aux.fork, 0);
        cudaStreamWaitEvent(g_aux.s2, g_aux.fork, 0);
    }
    detect_kernel<<<1, 1024, 0, sb>>>((const unsigned long long*)ei);
    convert_hist_kernel<<<(ET + 255) / 256, 256, 0, sb>>>(ei);
    scan_local_kernel<<<NB_SCAN, 1024, 0, sb>>>();
    scan_bsum_kernel<<<1, 64, 0, sb>>>();
    addoff_kernel<<<(N_NODES + 255) / 256, 256, 0, sb>>>();
    scatter_kernel<<<(ET + 255) / 256, 256, 0, sb>>>();
    if (g_aux.ok) cudaEventRecord(g_aux.join, g_aux.s2);

    // ---- main stream: layer-1 dense work (alpha fused into epilogue) ----
    gemm1_kernel<<<(N_NODES + 127) / 128, 256>>>(x, W1, as1, ad1);

    // ---- join: aggregation needs the CSR ----
    if (g_aux.ok) cudaStreamWaitEvent(0, g_aux.join, 0);
    agg1_csr_kernel<<<(N_NODES * 32 + 255) / 256, 256>>>(b1);

    // ---- layer 2 (alpha fused into epilogue) ----
    gemm2_kernel<<<(N_NODES + 127) / 128, 256>>>(W2, as2, ad2);
    agg2_csr_kernel<<<(N_NODES * 16 + 255) / 256, 256>>>(b2, out);
}

// round 16
// speedup vs baseline: 1.6022x; 1.0283x over previous
#include <cuda_runtime.h>
#include <cuda_bf16.h>
#include <math.h>

#define N_NODES 50000
#define E_EDGES 800000
#define ET (E_EDGES + N_NODES)   /* 850000 edges incl. self loops */
#define HID 128
#define HEADS 8
#define C1 16
#define OUT_DIM 64
#define NEG_SLOPE 0.2f
#define NB_SCAN ((N_NODES + 1023) / 1024)   /* 49 scan tiles */

// ---------------- scratch (device globals; no allocation) ----------------
__device__ __align__(16) float g_h1[N_NODES * HID];    // layer1 projection (fp32, for scores)
__device__ __align__(16) __nv_bfloat16 g_h1b[N_NODES * HID];   // bf16 copy (gather payload)
__device__ __align__(16) float g_out1[N_NODES * HID];  // layer1 output (post-ELU)
__device__ __align__(16) float g_h2[N_NODES * OUT_DIM];
__device__ __align__(16) __nv_bfloat16 g_h2b[N_NODES * OUT_DIM];
__device__ float g_as1[N_NODES * HEADS];
__device__ float g_ad1[N_NODES * HEADS];
__device__ float g_as2[N_NODES];
__device__ float g_ad2[N_NODES];
__device__ int   g_src[ET];
__device__ int   g_dst[ET];
__device__ int   g_es[ET];          // src ids sorted by dst (CSR values)
__device__ int   g_cnt[N_NODES];    // zero at call entry (scan_local re-zeroes)
__device__ int   g_off[N_NODES + 1];
__device__ int   g_cur[N_NODES];
__device__ int   g_bsum[NB_SCAN];

// ---------------- side stream for CSR-build / GEMM overlap ----------------
namespace {
struct AuxStreams {
    cudaStream_t s2 = 0;
    cudaEvent_t  fork = 0, join = 0;
    bool ok = false;
    AuxStreams() {
        if (cudaStreamCreateWithFlags(&s2, cudaStreamNonBlocking) == cudaSuccess &&
            cudaEventCreateWithFlags(&fork, cudaEventDisableTiming) == cudaSuccess &&
            cudaEventCreateWithFlags(&join, cudaEventDisableTiming) == cudaSuccess) {
            ok = true;
        } else {
            s2 = 0;
            ok = false;
        }
    }
};
AuxStreams g_aux;
}

// ---------------- tf32 helpers ----------------
__device__ __forceinline__ float f2tf32f(float f) {
    unsigned r;
    asm("cvt.rna.tf32.f32 %0, %1;" : "=r"(r) : "f"(f));
    return __uint_as_float(r);
}
__device__ __forceinline__ void mma_tf32(float* d, unsigned a0, unsigned a1,
                                         unsigned a2, unsigned a3,
                                         unsigned b0, unsigned b1) {
    asm volatile(
        "mma.sync.aligned.m16n8k8.row.col.f32.tf32.tf32.f32 "
        "{%0,%1,%2,%3}, {%4,%5,%6,%7}, {%8,%9}, {%0,%1,%2,%3};"
        : "+f"(d[0]), "+f"(d[1]), "+f"(d[2]), "+f"(d[3])
        : "r"(a0), "r"(a1), "r"(a2), "r"(a3), "r"(b0), "r"(b1));
}

// decode edges (+self loops), stage src/dst, histogram destinations.
// Dtype detection is inlined per-block: the first 8KB of the edge buffer is
// sampled as int64; any out-of-range value => data is int32. Deterministic
// and identical across blocks (L2-resident after first touch). Removes the
// serial detect launch.
__global__ void __launch_bounds__(256) convert_hist_kernel(const void* __restrict__ ei) {
    __shared__ int bad;
    if (threadIdx.x == 0) bad = 0;
    __syncthreads();
    {
        const unsigned long long* e64 = (const unsigned long long*)ei;
        int any = 0;
#pragma unroll
        for (int j = 0; j < 4; j++) {
            unsigned long long v = e64[threadIdx.x * 4 + j];
            any |= (v >= (unsigned long long)N_NODES);
        }
        if (any) atomicOr(&bad, 1);
    }
    __syncthreads();
    int is64 = !bad;

    int t = blockIdx.x * blockDim.x + threadIdx.x;
    if (t >= ET) return;
    int s, d;
    if (t >= E_EDGES) {
        s = d = t - E_EDGES;
    } else if (is64) {
        const long long* p = (const long long*)ei;
        s = (int)p[t];
        d = (int)p[E_EDGES + t];
    } else {
        const int* p = (const int*)ei;
        s = p[t];
        d = p[E_EDGES + t];
    }
    g_src[t] = s;
    g_dst[t] = d;
    atomicAdd(&g_cnt[d], 1);
}

// ---------------- exclusive scan of g_cnt (2 kernels) ----------------
// phase 1: per-tile exclusive scan + tile total; zeroes counts in place.
__global__ void scan_local_kernel() {
    __shared__ int sh[1024];
    int t = threadIdx.x;
    int i = blockIdx.x * 1024 + t;
    int v = 0;
    if (i < N_NODES) {
        v = g_cnt[i];
        g_cnt[i] = 0;    // keep zero-on-entry invariant for next replay
    }
    sh[t] = v;
    __syncthreads();
    for (int o = 1; o < 1024; o <<= 1) {
        int cur = sh[t];
        int idx = (t >= o) ? (t - o) : 0;   // always valid (no speculative OOB LDS)
        int u = sh[idx];
        u = (t >= o) ? u : 0;
        __syncthreads();
        sh[t] = cur + u;
        __syncthreads();
    }
    if (i < N_NODES) g_off[i] = sh[t] - v;  // exclusive within tile
    if (t == 1023) g_bsum[blockIdx.x] = sh[1023];
}

// phase 2: add tile-prefix offsets; the 49-element bsum scan is folded in
// (each thread sums g_bsum[0..tile-1] from cache — removes a serial launch).
__global__ void addoff_kernel() {
    __shared__ int bs[NB_SCAN];
    for (int j = threadIdx.x; j < NB_SCAN; j += blockDim.x) bs[j] = g_bsum[j];
    __syncthreads();
    int i = blockIdx.x * blockDim.x + threadIdx.x;
    if (i < N_NODES) {
        int tile = i >> 10;
        int boff = 0;
        for (int j = 0; j < tile; j++) boff += bs[j];
        int o = g_off[i] + boff;
        g_off[i] = o;
        g_cur[i] = o;
    }
    if (i == 0) g_off[N_NODES] = ET;
}

__global__ void scatter_kernel() {
    int t = blockIdx.x * blockDim.x + threadIdx.x;
    if (t >= ET) return;
    int d = g_dst[t];
    int pos = atomicAdd(&g_cur[d], 1);
    g_es[pos] = g_src[t];
}

// ---------------- tf32 GEMM layer 1 + fused alpha epilogue -----------------
__global__ void __launch_bounds__(256) gemm1_kernel(const float* __restrict__ X,
                                                    const float* __restrict__ W,
                                                    const float* __restrict__ a_s,
                                                    const float* __restrict__ a_d) {
    __shared__ float Xs[128][36];   // pad 36: A-frag bank = (4g+tg), conflict-free
    __shared__ float Ws[32][136];   // pad 136: B-frag bank = (8tg+g), conflict-free
    const int tid = threadIdx.x;
    const int warp = tid >> 5, lane = tid & 31;
    const int g = lane >> 2, tg = lane & 3;
    const int base = blockIdx.x * 128;
    const int row0 = warp * 16;

    float d[16][4];
#pragma unroll
    for (int nt = 0; nt < 16; nt++)
#pragma unroll
        for (int j = 0; j < 4; j++) d[nt][j] = 0.0f;

    const int lr = tid >> 1, lh = tid & 1;   // X loader
    const int kw = tid >> 3, seg = tid & 7;  // W loader

    for (int k0 = 0; k0 < 128; k0 += 32) {
        {
            int node = base + lr; if (node >= N_NODES) node = N_NODES - 1;
            const float4* xr = (const float4*)(X + (size_t)node * 128 + k0 + lh * 16);
#pragma unroll
            for (int c = 0; c < 4; c++) {
                float4 v = xr[c];
                int kk = lh * 16 + c * 4;
                Xs[lr][kk + 0] = f2tf32f(v.x); Xs[lr][kk + 1] = f2tf32f(v.y);
                Xs[lr][kk + 2] = f2tf32f(v.z); Xs[lr][kk + 3] = f2tf32f(v.w);
            }
        }
        {
            const float4* wr = (const float4*)(W + (size_t)(k0 + kw) * 128 + seg * 16);
#pragma unroll
            for (int c = 0; c < 4; c++) {
                float4 v = wr[c];
                int cc = seg * 16 + c * 4;
                Ws[kw][cc + 0] = f2tf32f(v.x); Ws[kw][cc + 1] = f2tf32f(v.y);
                Ws[kw][cc + 2] = f2tf32f(v.z); Ws[kw][cc + 3] = f2tf32f(v.w);
            }
        }
        __syncthreads();
#pragma unroll
        for (int ks = 0; ks < 4; ks++) {
            int kk = ks * 8;
            unsigned a0 = __float_as_uint(Xs[row0 + g][kk + tg]);
            unsigned a1 = __float_as_uint(Xs[row0 + g + 8][kk + tg]);
            unsigned a2 = __float_as_uint(Xs[row0 + g][kk + tg + 4]);
            unsigned a3 = __float_as_uint(Xs[row0 + g + 8][kk + tg + 4]);
#pragma unroll
            for (int nt = 0; nt < 16; nt++) {
                unsigned b0 = __float_as_uint(Ws[kk + tg][nt * 8 + g]);
                unsigned b1 = __float_as_uint(Ws[kk + tg + 4][nt * 8 + g]);
                mma_tf32(d[nt], a0, a1, a2, a3, b0, b1);
            }
        }
        __syncthreads();
    }

    const unsigned FULL = 0xffffffffu;
    int n1 = base + row0 + g;
    int n2 = n1 + 8;

    // fused alpha: per-lane partial dots with a_s/a_d, reduced over tg lanes
    float ps1[8], pd1[8], ps2[8], pd2[8];
#pragma unroll
    for (int hh = 0; hh < 8; hh++) { ps1[hh] = pd1[hh] = ps2[hh] = pd2[hh] = 0.0f; }
#pragma unroll
    for (int nt = 0; nt < 16; nt++) {
        int c = nt * 8 + 2 * tg;
        float sa0 = __ldg(&a_s[c]), sa1 = __ldg(&a_s[c + 1]);
        float da0 = __ldg(&a_d[c]), da1 = __ldg(&a_d[c + 1]);
        int hh = nt >> 1;
        ps1[hh] += d[nt][0] * sa0 + d[nt][1] * sa1;
        pd1[hh] += d[nt][0] * da0 + d[nt][1] * da1;
        ps2[hh] += d[nt][2] * sa0 + d[nt][3] * sa1;
        pd2[hh] += d[nt][2] * da0 + d[nt][3] * da1;
    }
#pragma unroll
    for (int hh = 0; hh < 8; hh++) {
        ps1[hh] += __shfl_xor_sync(FULL, ps1[hh], 1);
        ps1[hh] += __shfl_xor_sync(FULL, ps1[hh], 2);
        pd1[hh] += __shfl_xor_sync(FULL, pd1[hh], 1);
        pd1[hh] += __shfl_xor_sync(FULL, pd1[hh], 2);
        ps2[hh] += __shfl_xor_sync(FULL, ps2[hh], 1);
        ps2[hh] += __shfl_xor_sync(FULL, ps2[hh], 2);
        pd2[hh] += __shfl_xor_sync(FULL, pd2[hh], 1);
        pd2[hh] += __shfl_xor_sync(FULL, pd2[hh], 2);
    }
    if (tg < 2) {
        if (n1 < N_NODES) {
#pragma unroll
            for (int hh = 0; hh < 8; hh++) {
                if (tg == 0) g_as1[n1 * 8 + hh] = ps1[hh];
                else         g_ad1[n1 * 8 + hh] = pd1[hh];
            }
        }
        if (n2 < N_NODES) {
#pragma unroll
            for (int hh = 0; hh < 8; hh++) {
                if (tg == 0) g_as1[n2 * 8 + hh] = ps2[hh];
                else         g_ad1[n2 * 8 + hh] = pd2[hh];
            }
        }
    }

    // main result stores (fp32 + bf16 copy)
#pragma unroll
    for (int nt = 0; nt < 16; nt++) {
        int c = nt * 8 + 2 * tg;
        if (n1 < N_NODES) {
            *(float2*)&g_h1[(size_t)n1 * 128 + c] = make_float2(d[nt][0], d[nt][1]);
            __nv_bfloat162 p = __floats2bfloat162_rn(d[nt][0], d[nt][1]);
            *(unsigned*)&g_h1b[(size_t)n1 * 128 + c] = *(unsigned*)&p;
        }
        if (n2 < N_NODES) {
            *(float2*)&g_h1[(size_t)n2 * 128 + c] = make_float2(d[nt][2], d[nt][3]);
            __nv_bfloat162 p = __floats2bfloat162_rn(d[nt][2], d[nt][3]);
            *(unsigned*)&g_h1b[(size_t)n2 * 128 + c] = *(unsigned*)&p;
        }
    }
}

// ---------------- tf32 GEMM layer 2 + fused alpha epilogue -----------------
__global__ void __launch_bounds__(256) gemm2_kernel(const float* __restrict__ W,
                                                    const float* __restrict__ a_s,
                                                    const float* __restrict__ a_d) {
    __shared__ float Xs[128][36];
    __shared__ float Ws[32][72];    // pad 72: B-frag bank = (8tg+g), conflict-free
    const int tid = threadIdx.x;
    const int warp = tid >> 5, lane = tid & 31;
    const int g = lane >> 2, tg = lane & 3;
    const int base = blockIdx.x * 128;
    const int row0 = warp * 16;

    float d[8][4];
#pragma unroll
    for (int nt = 0; nt < 8; nt++)
#pragma unroll
        for (int j = 0; j < 4; j++) d[nt][j] = 0.0f;

    const int lr = tid >> 1, lh = tid & 1;   // X loader
    const int kw = tid >> 3, seg = tid & 7;  // W loader

    for (int k0 = 0; k0 < 128; k0 += 32) {
        {
            int node = base + lr; if (node >= N_NODES) node = N_NODES - 1;
            const float4* xr = (const float4*)(g_out1 + (size_t)node * 128 + k0 + lh * 16);
#pragma unroll
            for (int c = 0; c < 4; c++) {
                float4 v = xr[c];
                int kk = lh * 16 + c * 4;
                Xs[lr][kk + 0] = f2tf32f(v.x); Xs[lr][kk + 1] = f2tf32f(v.y);
                Xs[lr][kk + 2] = f2tf32f(v.z); Xs[lr][kk + 3] = f2tf32f(v.w);
            }
        }
        {
            const float4* wr = (const float4*)(W + (size_t)(k0 + kw) * 64 + seg * 8);
#pragma unroll
            for (int c = 0; c < 2; c++) {
                float4 v = wr[c];
                int cc = seg * 8 + c * 4;
                Ws[kw][cc + 0] = f2tf32f(v.x); Ws[kw][cc + 1] = f2tf32f(v.y);
                Ws[kw][cc + 2] = f2tf32f(v.z); Ws[kw][cc + 3] = f2tf32f(v.w);
            }
        }
        __syncthreads();
#pragma unroll
        for (int ks = 0; ks < 4; ks++) {
            int kk = ks * 8;
            unsigned a0 = __float_as_uint(Xs[row0 + g][kk + tg]);
            unsigned a1 = __float_as_uint(Xs[row0 + g + 8][kk + tg]);
            unsigned a2 = __float_as_uint(Xs[row0 + g][kk + tg + 4]);
            unsigned a3 = __float_as_uint(Xs[row0 + g + 8][kk + tg + 4]);
#pragma unroll
            for (int nt = 0; nt < 8; nt++) {
                unsigned b0 = __float_as_uint(Ws[kk + tg][nt * 8 + g]);
                unsigned b1 = __float_as_uint(Ws[kk + tg + 4][nt * 8 + g]);
                mma_tf32(d[nt], a0, a1, a2, a3, b0, b1);
            }
        }
        __syncthreads();
    }

    const unsigned FULL = 0xffffffffu;
    int n1 = base + row0 + g;
    int n2 = n1 + 8;

    float ps1 = 0.f, pd1 = 0.f, ps2 = 0.f, pd2 = 0.f;
#pragma unroll
    for (int nt = 0; nt < 8; nt++) {
        int c = nt * 8 + 2 * tg;
        float sa0 = __ldg(&a_s[c]), sa1 = __ldg(&a_s[c + 1]);
        float da0 = __ldg(&a_d[c]), da1 = __ldg(&a_d[c + 1]);
        ps1 += d[nt][0] * sa0 + d[nt][1] * sa1;
        pd1 += d[nt][0] * da0 + d[nt][1] * da1;
        ps2 += d[nt][2] * sa0 + d[nt][3] * sa1;
        pd2 += d[nt][2] * da0 + d[nt][3] * da1;
    }
    ps1 += __shfl_xor_sync(FULL, ps1, 1); ps1 += __shfl_xor_sync(FULL, ps1, 2);
    pd1 += __shfl_xor_sync(FULL, pd1, 1); pd1 += __shfl_xor_sync(FULL, pd1, 2);
    ps2 += __shfl_xor_sync(FULL, ps2, 1); ps2 += __shfl_xor_sync(FULL, ps2, 2);
    pd2 += __shfl_xor_sync(FULL, pd2, 1); pd2 += __shfl_xor_sync(FULL, pd2, 2);
    if (tg == 0) {
        if (n1 < N_NODES) { g_as2[n1] = ps1; g_ad2[n1] = pd1; }
        if (n2 < N_NODES) { g_as2[n2] = ps2; g_ad2[n2] = pd2; }
    }

#pragma unroll
    for (int nt = 0; nt < 8; nt++) {
        int c = nt * 8 + 2 * tg;
        if (n1 < N_NODES) {
            *(float2*)&g_h2[(size_t)n1 * 64 + c] = make_float2(d[nt][0], d[nt][1]);
            __nv_bfloat162 p = __floats2bfloat162_rn(d[nt][0], d[nt][1]);
            *(unsigned*)&g_h2b[(size_t)n1 * 64 + c] = *(unsigned*)&p;
        }
        if (n2 < N_NODES) {
            *(float2*)&g_h2[(size_t)n2 * 64 + c] = make_float2(d[nt][2], d[nt][3]);
            __nv_bfloat162 p = __floats2bfloat162_rn(d[nt][2], d[nt][3]);
            *(unsigned*)&g_h2b[(size_t)n2 * 64 + c] = *(unsigned*)&p;
        }
    }
}

// ---------------- CSR aggregation, layer 1 (R11 form: bf16 8B gathers) -----
__global__ void __launch_bounds__(256) agg1_csr_kernel(const float* __restrict__ b1) {
    const unsigned FULL = 0xffffffffu;
    int n = (blockIdx.x * blockDim.x + threadIdx.x) >> 5;
    int lane = threadIdx.x & 31;
    if (n >= N_NODES) return;
    int beg = g_off[n], end = g_off[n + 1];
    int h = lane & 7;          // head for score phase
    int eslot = lane >> 3;     // 0..3: which edge of the group
    float ad = g_ad1[n * HEADS + h];
    float4 acc = make_float4(0.f, 0.f, 0.f, 0.f);
    float den = 0.0f;

    int cnt = end - beg;
    int nfull = cnt & ~3;
    int pfull = beg + nfull;

    for (int p = beg; p < pfull; p += 4) {
        int src = g_es[p + eslot];
        float sc = g_as1[src * HEADS + h] + ad;
        sc = (sc >= 0.0f) ? sc : NEG_SLOPE * sc;
        float e = expf(sc);
        den += e;
#pragma unroll
        for (int j = 0; j < 4; j++) {
            int srcj = __shfl_sync(FULL, src, j * 8);
            float ej = __shfl_sync(FULL, e, j * 8 + (lane >> 2));
            uint2 raw = ((const uint2*)(g_h1b + (size_t)srcj * 128))[lane];
            float2 f0 = __bfloat1622float2(*(__nv_bfloat162*)&raw.x);
            float2 f1 = __bfloat1622float2(*(__nv_bfloat162*)&raw.y);
            acc.x += f0.x * ej; acc.y += f0.y * ej;
            acc.z += f1.x * ej; acc.w += f1.y * ej;
        }
    }
    int rem = cnt - nfull;     // 0..3, uniform across warp
    if (rem) {
        int eidx = pfull + eslot;
        int src = g_es[(eidx < end) ? eidx : beg];
        float sc = g_as1[src * HEADS + h] + ad;
        sc = (sc >= 0.0f) ? sc : NEG_SLOPE * sc;
        float e = (eslot < rem) ? expf(sc) : 0.0f;
        den += e;
        for (int j = 0; j < rem; j++) {
            int srcj = __shfl_sync(FULL, src, j * 8);
            float ej = __shfl_sync(FULL, e, j * 8 + (lane >> 2));
            uint2 raw = ((const uint2*)(g_h1b + (size_t)srcj * 128))[lane];
            float2 f0 = __bfloat1622float2(*(__nv_bfloat162*)&raw.x);
            float2 f1 = __bfloat1622float2(*(__nv_bfloat162*)&raw.y);
            acc.x += f0.x * ej; acc.y += f0.y * ej;
            acc.z += f1.x * ej; acc.w += f1.y * ej;
        }
    }
    den += __shfl_xor_sync(FULL, den, 8);
    den += __shfl_xor_sync(FULL, den, 16);
    float dh = __shfl_sync(FULL, den, lane >> 2);
    float inv = 1.0f / dh;
    const float4 bb = ((const float4*)b1)[lane];
    float4 r;
    r.x = acc.x * inv + bb.x; r.y = acc.y * inv + bb.y;
    r.z = acc.z * inv + bb.z; r.w = acc.w * inv + bb.w;
    r.x = (r.x > 0.f) ? r.x : expm1f(r.x);
    r.y = (r.y > 0.f) ? r.y : expm1f(r.y);
    r.z = (r.z > 0.f) ? r.z : expm1f(r.z);
    r.w = (r.w > 0.f) ? r.w : expm1f(r.w);
    ((float4*)(g_out1 + (size_t)n * 128))[lane] = r;
}

// ---------------- CSR aggregation + log_softmax, layer 2 (R11 form) --------
__global__ void __launch_bounds__(256) agg2_csr_kernel(const float* __restrict__ b2,
                                                       float* __restrict__ out) {
    int hw = (blockIdx.x * blockDim.x + threadIdx.x) >> 4;  // node id
    int lane = threadIdx.x & 31;
    int l = lane & 15;
    const unsigned mask = 0xffffu << (lane & 16);  // own half-warp only (R5 lesson)
    if (hw >= N_NODES) return;
    int n = hw;
    int beg = g_off[n], end = g_off[n + 1];
    float ad = g_ad2[n];
    float4 acc = make_float4(0.f, 0.f, 0.f, 0.f);
    float den = 0.0f;

    int cnt = end - beg;
    int nfull = cnt & ~15;
    int pfull = beg + nfull;

    for (int p = beg; p < pfull; p += 16) {
        int src = g_es[p + l];
        float sc = g_as2[src] + ad;
        sc = (sc >= 0.0f) ? sc : NEG_SLOPE * sc;
        float e = expf(sc);
        den += e;
#pragma unroll
        for (int j = 0; j < 16; j++) {
            int srcj = __shfl_sync(mask, src, j, 16);
            float ej = __shfl_sync(mask, e, j, 16);
            uint2 raw = ((const uint2*)(g_h2b + (size_t)srcj * 64))[l];
            float2 f0 = __bfloat1622float2(*(__nv_bfloat162*)&raw.x);
            float2 f1 = __bfloat1622float2(*(__nv_bfloat162*)&raw.y);
            acc.x += f0.x * ej; acc.y += f0.y * ej;
            acc.z += f1.x * ej; acc.w += f1.y * ej;
        }
    }
    int rem = cnt - nfull;   // 0..15, uniform across half-warp
    if (rem) {
        int eidx = pfull + l;
        int src = g_es[(eidx < end) ? eidx : beg];
        float sc = g_as2[src] + ad;
        sc = (sc >= 0.0f) ? sc : NEG_SLOPE * sc;
        float e = (l < rem) ? expf(sc) : 0.0f;
        den += e;
        for (int j = 0; j < rem; j++) {
            int srcj = __shfl_sync(mask, src, j, 16);
            float ej = __shfl_sync(mask, e, j, 16);
            uint2 raw = ((const uint2*)(g_h2b + (size_t)srcj * 64))[l];
            float2 f0 = __bfloat1622float2(*(__nv_bfloat162*)&raw.x);
            float2 f1 = __bfloat1622float2(*(__nv_bfloat162*)&raw.y);
            acc.x += f0.x * ej; acc.y += f0.y * ej;
            acc.z += f1.x * ej; acc.w += f1.y * ej;
        }
    }
#pragma unroll
    for (int o = 8; o; o >>= 1) den += __shfl_xor_sync(mask, den, o, 16);
    float inv = 1.0f / den;
    const float4 bb = ((const float4*)b2)[l];
    float v[4];
    v[0] = acc.x * inv + bb.x; v[1] = acc.y * inv + bb.y;
    v[2] = acc.z * inv + bb.z; v[3] = acc.w * inv + bb.w;
    float m = fmaxf(fmaxf(v[0], v[1]), fmaxf(v[2], v[3]));
#pragma unroll
    for (int o = 8; o; o >>= 1) m = fmaxf(m, __shfl_xor_sync(mask, m, o, 16));
    float s = expf(v[0] - m) + expf(v[1] - m) + expf(v[2] - m) + expf(v[3] - m);
#pragma unroll
    for (int o = 8; o; o >>= 1) s += __shfl_xor_sync(mask, s, o, 16);
    float lse = m + logf(s);
    ((float4*)(out + (size_t)n * 64))[l] =
        make_float4(v[0] - lse, v[1] - lse, v[2] - lse, v[3] - lse);
}

// ---------------- launch ----------------
extern "C" void kernel_launch(void* const* d_in, const int* in_sizes, int n_in,
                              void* d_out, int out_size) {
    const float* x   = (const float*)d_in[0];
    const void*  ei  = d_in[1];
    const float* W1  = (const float*)d_in[2];
    const float* as1 = (const float*)d_in[3];
    const float* ad1 = (const float*)d_in[4];
    const float* b1  = (const float*)d_in[5];
    const float* W2  = (const float*)d_in[6];
    const float* as2 = (const float*)d_in[7];
    const float* ad2 = (const float*)d_in[8];
    const float* b2  = (const float*)d_in[9];
    float* out = (float*)d_out;

    // ---- fork: CSR build on side stream (4 launches), overlapping gemm1 ----
    cudaStream_t sb = g_aux.ok ? g_aux.s2 : 0;
    if (g_aux.ok) {
        cudaEventRecord(g_aux.fork, 0);
        cudaStreamWaitEvent(g_aux.s2, g_aux.fork, 0);
    }
    convert_hist_kernel<<<(ET + 255) / 256, 256, 0, sb>>>(ei);
    scan_local_kernel<<<NB_SCAN, 1024, 0, sb>>>();
    addoff_kernel<<<(N_NODES + 255) / 256, 256, 0, sb>>>();
    scatter_kernel<<<(ET + 255) / 256, 256, 0, sb>>>();
    if (g_aux.ok) cudaEventRecord(g_aux.join, g_aux.s2);

    // ---- main stream: layer-1 dense work (alpha fused into epilogue) ----
    gemm1_kernel<<<(N_NODES + 127) / 128, 256>>>(x, W1, as1, ad1);

    // ---- join: aggregation needs the CSR ----
    if (g_aux.ok) cudaStreamWaitEvent(0, g_aux.join, 0);
    agg1_csr_kernel<<<(N_NODES * 32 + 255) / 256, 256>>>(b1);

    // ---- layer 2 (alpha fused into epilogue) ----
    gemm2_kernel<<<(N_NODES + 127) / 128, 256>>>(W2, as2, ad2);
    agg2_csr_kernel<<<(N_NODES * 16 + 255) / 256, 256>>>(b2, out);
}